// round 2
// baseline (speedup 1.0000x reference)
#include <cuda_runtime.h>
#include <math.h>

#define T_LEN 4096
#define B_SZ  16

// ---------------- scratch (device globals; no allocation allowed) ----------------
__device__ float g_bufA[16*512*4096];
__device__ float g_bufB[16*512*4096];
__device__ float g_ye  [16*128*4096];
__device__ float g_z   [16*64*4096];
__device__ float g_zvq [16*64*4096];
__device__ float g_wt  [640*5*1024];
__device__ float g_cbt [64*512];
__device__ float g_cbn [512];
__device__ float g_spk [128*128];
__device__ int   g_idx [16*4096];

// ---------------- small helper kernels ----------------
__global__ void transpose_x_k(const float* __restrict__ x, float* __restrict__ xt) {
    __shared__ float tile[32][33];
    int b = blockIdx.z;
    int t0 = blockIdx.x*32, f0 = blockIdx.y*32;
    int tx = threadIdx.x, ty = threadIdx.y;
    for (int j = ty; j < 32; j += 8) {
        int t = t0 + j, f = f0 + tx;
        tile[j][tx] = (f < 80) ? x[((size_t)b*T_LEN + t)*80 + f] : 0.f;
    }
    __syncthreads();
    for (int j = ty; j < 32; j += 8) {
        int f = f0 + j, t = t0 + tx;
        if (f < 80) xt[((size_t)b*80 + f)*T_LEN + t] = tile[tx][j];
    }
}

__global__ void spknorm_k(const float* __restrict__ spk, float* __restrict__ o) {
    __shared__ float red[128];
    int r = blockIdx.x, t = threadIdx.x;
    float v = spk[r*128 + t];
    red[t] = v*v;
    __syncthreads();
    for (int s = 64; s > 0; s >>= 1) { if (t < s) red[t] += red[t+s]; __syncthreads(); }
    o[r*128 + t] = v * rsqrtf(red[0]);
}

__global__ void cbnorm_k(const float* __restrict__ cb, float* __restrict__ n) {
    int c = blockIdx.x*128 + threadIdx.x;
    if (c < 512) {
        float s = 0.f;
        for (int d = 0; d < 64; d++) { float v = cb[c*64 + d]; s += v*v; }
        n[c] = s;
    }
}

__global__ void ye_gather_k(const int* __restrict__ y, const float* __restrict__ spk,
                            float* __restrict__ ye) {
    int b = blockIdx.y;
    int t = blockIdx.x*32 + (threadIdx.x & 31);
    int w = threadIdx.x >> 5;
    int yi = y[(size_t)b*T_LEN + t];
    for (int c = w; c < 128; c += 8)
        ye[((size_t)b*128 + c)*T_LEN + t] = spk[yi*128 + c];
}

__global__ void zvq_gather_k(const int* __restrict__ idx, const float* __restrict__ cb,
                             float* __restrict__ zvq) {
    int b = blockIdx.y;
    int t = blockIdx.x*32 + (threadIdx.x & 31);
    int w = threadIdx.x >> 5;
    int ii = idx[(size_t)b*T_LEN + t];
    for (int d = w; d < 64; d += 8)
        zvq[((size_t)b*64 + d)*T_LEN + t] = cb[ii*64 + d];
}

// weight transform -> wt[ci][k][co] contiguous (dec=1 also does ConvT flip/transpose)
__global__ void wtrans_k(const float* __restrict__ w, float* __restrict__ wt,
                         int CIN, int COUT, int K, int dec) {
    int e = blockIdx.x*256 + threadIdx.x;
    int total = CIN*COUT*K;
    if (e >= total) return;
    int co = e % COUT; int r = e / COUT; int k = r % K; int ci = r / K;
    wt[e] = dec ? w[((size_t)ci*COUT + co)*K + (K-1-k)]
                : w[((size_t)co*CIN + ci)*K + k];
}

// ---------------- generic fused conv kernel ----------------
// EPI: 0=bias only ([b][co][t]), 1=LN+LeakyReLU, 2=LN+GLU (writes COUT/2 ch),
//      3=VQ argmin (bias=||c||^2, writes int idx), 4=bias only transposed ([b][t][co])
template<int CIN1,int CIN2,int COUT,int KS,int CI_BLK,int G_CO,int TPT,int EPI>
__global__ __launch_bounds__(256,2) void conv_k(
    const float* __restrict__ in1, const float* __restrict__ in2,
    const float* __restrict__ wt, const float* __restrict__ bias,
    const float* __restrict__ gamma, const float* __restrict__ beta,
    float* __restrict__ out, int* __restrict__ oidx)
{
    constexpr int CIN  = CIN1 + CIN2;
    constexpr int PAD  = (KS - 1) / 2;
    constexpr int G_T  = 256 / G_CO;
    constexpr int TT   = G_T * TPT;
    constexpr int CPT  = COUT / G_CO;
    constexpr int RIN  = TPT + KS - 1;
    constexpr int IROW = TT + KS - 1;
    constexpr int WELEMS = CI_BLK * KS * COUT;
    constexpr int IELEMS = CI_BLK * IROW;
    constexpr int NCB  = CIN / CI_BLK;
    constexpr bool NEED_RED = (EPI==1 || EPI==2 || EPI==3);
    constexpr int RSTRIDE = G_CO + 1;

    extern __shared__ float smem[];
    float* sW = smem;
    float* sI = sW + WELEMS;
    float* sRa = sI + IELEMS;                 // TT*RSTRIDE
    float* sRb = sRa + (NEED_RED ? TT*RSTRIDE : 0);
    float* sMean = sRb + (NEED_RED ? TT*RSTRIDE : 0);
    float* sRstd = sMean + (NEED_RED ? TT : 0);

    const int tid = threadIdx.x;
    const int cg  = tid % G_CO;
    const int tg  = tid / G_CO;
    const int b   = blockIdx.y;
    const int t0  = blockIdx.x * TT;

    float acc[CPT][TPT];
    #pragma unroll
    for (int i = 0; i < CPT; i++)
        #pragma unroll
        for (int t = 0; t < TPT; t++) acc[i][t] = 0.f;

    for (int cb = 0; cb < NCB; cb++) {
        __syncthreads();
        const float* wsrc = wt + (size_t)cb * WELEMS;
        for (int e = tid; e < WELEMS; e += 256) sW[e] = wsrc[e];
        for (int e = tid; e < IELEMS; e += 256) {
            int ci = e / IROW, j = e % IROW;
            int t  = t0 - PAD + j;
            int cig = cb*CI_BLK + ci;
            float v = 0.f;
            if (t >= 0 && t < T_LEN) {
                if (CIN2 == 0 || cig < CIN1)
                    v = in1[((size_t)b*CIN1 + cig)*T_LEN + t];
                else
                    v = in2[((size_t)b*CIN2 + (cig - CIN1))*T_LEN + t];
            }
            sI[e] = v;
        }
        __syncthreads();

        #pragma unroll 1
        for (int ci = 0; ci < CI_BLK; ci++) {
            float rin[RIN];
            #pragma unroll
            for (int j = 0; j < RIN; j++) rin[j] = sI[ci*IROW + tg*TPT + j];
            #pragma unroll
            for (int k = 0; k < KS; k++) {
                #pragma unroll
                for (int i = 0; i < CPT; i++) {
                    float wv = sW[(ci*KS + k)*COUT + cg + G_CO*i];
                    #pragma unroll
                    for (int t = 0; t < TPT; t++)
                        acc[i][t] = fmaf(wv, rin[t + k], acc[i][t]);
                }
            }
        }
    }

    if constexpr (EPI == 3) {
        // VQ argmin: score = ||c||^2 - 2 * (z . c)
        float bv[CPT];
        #pragma unroll
        for (int i = 0; i < CPT; i++) bv[i] = bias[cg + G_CO*i];
        int* sRi = (int*)sRb;
        #pragma unroll
        for (int t = 0; t < TPT; t++) {
            float best = 3.4e38f; int bi = 0;
            #pragma unroll
            for (int i = 0; i < CPT; i++) {
                float v = bv[i] - 2.f*acc[i][t];
                int ii = cg + G_CO*i;
                if (v < best || (v == best && ii < bi)) { best = v; bi = ii; }
            }
            int tl = tg*TPT + t;
            sRa[tl*RSTRIDE + cg] = best;
            sRi[tl*RSTRIDE + cg] = bi;
        }
        __syncthreads();
        if (tid < TT) {
            float best = 3.4e38f; int bi = 0;
            for (int g = 0; g < G_CO; g++) {
                float v = sRa[tid*RSTRIDE + g]; int ii = sRi[tid*RSTRIDE + g];
                if (v < best || (v == best && ii < bi)) { best = v; bi = ii; }
            }
            oidx[(size_t)b*T_LEN + t0 + tid] = bi;
        }
        return;
    } else {
        // add conv bias
        #pragma unroll
        for (int i = 0; i < CPT; i++) {
            float bv = bias[cg + G_CO*i];
            #pragma unroll
            for (int t = 0; t < TPT; t++) acc[i][t] += bv;
        }

        if constexpr (EPI == 1 || EPI == 2) {
            #pragma unroll
            for (int t = 0; t < TPT; t++) {
                float s = 0.f, q = 0.f;
                #pragma unroll
                for (int i = 0; i < CPT; i++) { float v = acc[i][t]; s += v; q += v*v; }
                int tl = tg*TPT + t;
                sRa[tl*RSTRIDE + cg] = s;
                sRb[tl*RSTRIDE + cg] = q;
            }
            __syncthreads();
            if (tid < TT) {
                float s = 0.f, q = 0.f;
                for (int g = 0; g < G_CO; g++) { s += sRa[tid*RSTRIDE + g]; q += sRb[tid*RSTRIDE + g]; }
                float m = s * (1.f/COUT);
                float v = q * (1.f/COUT) - m*m;
                sMean[tid] = m;
                sRstd[tid] = rsqrtf(v + 1e-5f);
            }
            __syncthreads();

            if constexpr (EPI == 1) {
                #pragma unroll
                for (int i = 0; i < CPT; i++) {
                    int co = cg + G_CO*i;
                    float ga = gamma[co], be = beta[co];
                    #pragma unroll
                    for (int t = 0; t < TPT; t++) {
                        int tl = tg*TPT + t;
                        float v = (acc[i][t] - sMean[tl]) * sRstd[tl] * ga + be;
                        v = v > 0.f ? v : 0.2f*v;
                        out[((size_t)b*COUT + co)*T_LEN + t0 + tl] = v;
                    }
                }
            } else { // GLU
                constexpr int H = CPT/2;
                #pragma unroll
                for (int i = 0; i < H; i++) {
                    int co = cg + G_CO*i;
                    int co2 = co + COUT/2;
                    float ga = gamma[co], be = beta[co];
                    float g2a = gamma[co2], b2 = beta[co2];
                    #pragma unroll
                    for (int t = 0; t < TPT; t++) {
                        int tl = tg*TPT + t;
                        float m = sMean[tl], r = sRstd[tl];
                        float a  = (acc[i][t]   - m) * r * ga  + be;
                        float gt = (acc[i+H][t] - m) * r * g2a + b2;
                        out[((size_t)b*(COUT/2) + co)*T_LEN + t0 + tl] = a * (1.f/(1.f + expf(-gt)));
                    }
                }
            }
        } else if constexpr (EPI == 0) {
            #pragma unroll
            for (int i = 0; i < CPT; i++) {
                int co = cg + G_CO*i;
                #pragma unroll
                for (int t = 0; t < TPT; t++)
                    out[((size_t)b*COUT + co)*T_LEN + t0 + tg*TPT + t] = acc[i][t];
            }
        } else { // EPI == 4, transposed write [b][t][co]
            #pragma unroll
            for (int i = 0; i < CPT; i++) {
                int co = cg + G_CO*i;
                #pragma unroll
                for (int t = 0; t < TPT; t++) {
                    int tl = tg*TPT + t;
                    out[((size_t)b*T_LEN + t0 + tl)*COUT + co] = acc[i][t];
                }
            }
        }
    }
}

// ---------------- host launch helper ----------------
#define LAUNCH_CONV(CIN1,CIN2,COUT,KS,CIB,GCO,TPT,EPI, in1,in2,wtp,biasp,gap,bep,outp,oidxp) do { \
    constexpr int GT_ = 256/(GCO); constexpr int TT_ = GT_*(TPT); \
    constexpr int WE_ = (CIB)*(KS)*(COUT); \
    constexpr int IE_ = (CIB)*(TT_+(KS)-1); \
    constexpr int RED_ = ((EPI)==1||(EPI)==2||(EPI)==3) ? (2*TT_*((GCO)+1) + 2*TT_) : 0; \
    constexpr int SB_ = (WE_+IE_+RED_)*4; \
    auto kf_ = &conv_k<CIN1,CIN2,COUT,KS,CIB,GCO,TPT,EPI>; \
    if (SB_ > 48*1024) cudaFuncSetAttribute(kf_, cudaFuncAttributeMaxDynamicSharedMemorySize, SB_); \
    kf_<<<dim3(T_LEN/TT_, B_SZ), 256, SB_>>>(in1,in2,wtp,biasp,gap,bep,outp,oidxp); \
} while (0)

extern "C" void kernel_launch(void* const* d_in, const int* in_sizes, int n_in,
                              void* d_out, int out_size) {
    (void)in_sizes; (void)n_in; (void)out_size;
    const float* x       = (const float*)d_in[0];
    const int*   y       = (const int*)  d_in[1];
    const float* enc_w1  = (const float*)d_in[2];
    const float* enc_b1  = (const float*)d_in[3];
    const float* enc_g1  = (const float*)d_in[4];
    const float* enc_bt1 = (const float*)d_in[5];
    const float* enc_w2  = (const float*)d_in[6];
    const float* enc_b2  = (const float*)d_in[7];
    const float* enc_g2  = (const float*)d_in[8];
    const float* enc_bt2 = (const float*)d_in[9];
    const float* enc_w3  = (const float*)d_in[10];
    const float* enc_b3  = (const float*)d_in[11];
    const float* enc_g3  = (const float*)d_in[12];
    const float* enc_bt3 = (const float*)d_in[13];
    const float* mlp_w   = (const float*)d_in[14];
    const float* mlp_b   = (const float*)d_in[15];
    const float* codebook= (const float*)d_in[16];
    const float* spk_emb = (const float*)d_in[17];
    const float* dec_w1  = (const float*)d_in[18];
    const float* dec_b1  = (const float*)d_in[19];
    const float* dec_g1  = (const float*)d_in[20];
    const float* dec_bt1 = (const float*)d_in[21];
    const float* dec_w2  = (const float*)d_in[22];
    const float* dec_b2  = (const float*)d_in[23];
    const float* dec_g2  = (const float*)d_in[24];
    const float* dec_bt2 = (const float*)d_in[25];
    const float* dec_w3  = (const float*)d_in[26];
    const float* dec_b3  = (const float*)d_in[27];
    float* outp = (float*)d_out;

    float *bufA, *bufB, *ye, *z, *zvq, *wt, *cbt, *cbn, *spk; int* idx;
    cudaGetSymbolAddress((void**)&bufA, g_bufA);
    cudaGetSymbolAddress((void**)&bufB, g_bufB);
    cudaGetSymbolAddress((void**)&ye,   g_ye);
    cudaGetSymbolAddress((void**)&z,    g_z);
    cudaGetSymbolAddress((void**)&zvq,  g_zvq);
    cudaGetSymbolAddress((void**)&wt,   g_wt);
    cudaGetSymbolAddress((void**)&cbt,  g_cbt);
    cudaGetSymbolAddress((void**)&cbn,  g_cbn);
    cudaGetSymbolAddress((void**)&spk,  g_spk);
    cudaGetSymbolAddress((void**)&idx,  g_idx);

    // x [B,T,F] -> [B,F,T]
    transpose_x_k<<<dim3(T_LEN/32, 3, B_SZ), dim3(32,8)>>>(x, bufA);
    // speaker embedding: normalize + gather
    spknorm_k<<<128, 128>>>(spk_emb, spk);
    ye_gather_k<<<dim3(T_LEN/32, B_SZ), 256>>>(y, spk, ye);

    // encoder 1: 80 -> 512, LN + LeakyReLU
    wtrans_k<<<(512*80*5 + 255)/256, 256>>>(enc_w1, wt, 80, 512, 5, 0);
    LAUNCH_CONV(80,0,512,5, 8,64,8, 1, bufA, (const float*)nullptr, wt, enc_b1, enc_g1, enc_bt1, bufB, (int*)nullptr);
    // encoder 2
    wtrans_k<<<(512*512*5 + 255)/256, 256>>>(enc_w2, wt, 512, 512, 5, 0);
    LAUNCH_CONV(512,0,512,5, 8,64,8, 1, bufB, (const float*)nullptr, wt, enc_b2, enc_g2, enc_bt2, bufA, (int*)nullptr);
    // encoder 3
    wtrans_k<<<(512*512*5 + 255)/256, 256>>>(enc_w3, wt, 512, 512, 5, 0);
    LAUNCH_CONV(512,0,512,5, 8,64,8, 1, bufA, (const float*)nullptr, wt, enc_b3, enc_g3, enc_bt3, bufB, (int*)nullptr);
    // mlp 1x1: 512 -> 64
    wtrans_k<<<(512*64 + 255)/256, 256>>>(mlp_w, wt, 512, 64, 1, 0);
    LAUNCH_CONV(512,0,64,1, 16,32,8, 0, bufB, (const float*)nullptr, wt, mlp_b, (const float*)nullptr, (const float*)nullptr, z, (int*)nullptr);
    // VQ: argmin over 512 codes
    wtrans_k<<<(64*512 + 255)/256, 256>>>(codebook, cbt, 64, 512, 1, 0);
    cbnorm_k<<<4, 128>>>(codebook, cbn);
    LAUNCH_CONV(64,0,512,1, 16,64,8, 3, z, (const float*)nullptr, cbt, cbn, (const float*)nullptr, (const float*)nullptr, (float*)nullptr, idx);
    zvq_gather_k<<<dim3(T_LEN/32, B_SZ), 256>>>(idx, codebook, zvq);
    // decoder 1: (64 + 128) -> 1024, LN + GLU -> 512
    wtrans_k<<<(192*1024*5 + 255)/256, 256>>>(dec_w1, wt, 192, 1024, 5, 1);
    LAUNCH_CONV(64,128,1024,5, 4,128,8, 2, zvq, ye, wt, dec_b1, dec_g1, dec_bt1, bufA, (int*)nullptr);
    // decoder 2: (512 + 128) -> 1024, LN + GLU -> 512
    wtrans_k<<<(640*1024*5 + 255)/256, 256>>>(dec_w2, wt, 640, 1024, 5, 1);
    LAUNCH_CONV(512,128,1024,5, 4,128,8, 2, bufA, ye, wt, dec_b2, dec_g2, dec_bt2, bufB, (int*)nullptr);
    // decoder 3: (512 + 128) -> 80, transposed write to [B,T,F]
    wtrans_k<<<(640*80*5 + 255)/256, 256>>>(dec_w3, wt, 640, 80, 5, 1);
    LAUNCH_CONV(512,128,80,5, 8,16,4, 4, bufB, ye, wt, dec_b3, (const float*)nullptr, (const float*)nullptr, outp, (int*)nullptr);
}

// round 3
// speedup vs baseline: 1.5308x; 1.5308x over previous
#include <cuda_runtime.h>
#include <math.h>

#define T_LEN 4096
#define B_SZ  16

// ---------------- scratch (device globals; no allocation allowed) ----------------
__device__ float g_bufA[16*512*4096];
__device__ float g_bufB[16*512*4096];
__device__ float g_ye  [16*128*4096];
__device__ float g_z   [16*64*4096];
__device__ float g_zvq [16*64*4096];
__device__ float g_wt  [640*5*1024];
__device__ float g_cbt [64*512];
__device__ float g_cbn [512];
__device__ float g_spk [128*128];
__device__ int   g_idx [16*4096];

// ---------------- small helper kernels ----------------
__global__ void transpose_x_k(const float* __restrict__ x, float* __restrict__ xt) {
    __shared__ float tile[32][33];
    int b = blockIdx.z;
    int t0 = blockIdx.x*32, f0 = blockIdx.y*32;
    int tx = threadIdx.x, ty = threadIdx.y;
    for (int j = ty; j < 32; j += 8) {
        int t = t0 + j, f = f0 + tx;
        tile[j][tx] = (f < 80) ? x[((size_t)b*T_LEN + t)*80 + f] : 0.f;
    }
    __syncthreads();
    for (int j = ty; j < 32; j += 8) {
        int f = f0 + j, t = t0 + tx;
        if (f < 80) xt[((size_t)b*80 + f)*T_LEN + t] = tile[tx][j];
    }
}

__global__ void spknorm_k(const float* __restrict__ spk, float* __restrict__ o) {
    __shared__ float red[128];
    int r = blockIdx.x, t = threadIdx.x;
    float v = spk[r*128 + t];
    red[t] = v*v;
    __syncthreads();
    for (int s = 64; s > 0; s >>= 1) { if (t < s) red[t] += red[t+s]; __syncthreads(); }
    o[r*128 + t] = v * rsqrtf(red[0]);
}

__global__ void cbnorm_k(const float* __restrict__ cb, float* __restrict__ n) {
    int c = blockIdx.x*128 + threadIdx.x;
    if (c < 512) {
        float s = 0.f;
        for (int d = 0; d < 64; d++) { float v = cb[c*64 + d]; s += v*v; }
        n[c] = s;
    }
}

__global__ void ye_gather_k(const int* __restrict__ y, const float* __restrict__ spk,
                            float* __restrict__ ye) {
    int b = blockIdx.y;
    int t = blockIdx.x*32 + (threadIdx.x & 31);
    int w = threadIdx.x >> 5;
    int yi = y[(size_t)b*T_LEN + t];
    for (int c = w; c < 128; c += 8)
        ye[((size_t)b*128 + c)*T_LEN + t] = spk[yi*128 + c];
}

__global__ void zvq_gather_k(const int* __restrict__ idx, const float* __restrict__ cb,
                             float* __restrict__ zvq) {
    int b = blockIdx.y;
    int t = blockIdx.x*32 + (threadIdx.x & 31);
    int w = threadIdx.x >> 5;
    int ii = idx[(size_t)b*T_LEN + t];
    for (int d = w; d < 64; d += 8)
        zvq[((size_t)b*64 + d)*T_LEN + t] = cb[ii*64 + d];
}

// weight transform -> wt[ci][k][co] contiguous (dec=1 also does ConvT flip/transpose)
__global__ void wtrans_k(const float* __restrict__ w, float* __restrict__ wt,
                         int CIN, int COUT, int K, int dec) {
    int e = blockIdx.x*256 + threadIdx.x;
    int total = CIN*COUT*K;
    if (e >= total) return;
    int co = e % COUT; int r = e / COUT; int k = r % K; int ci = r / K;
    wt[e] = dec ? w[((size_t)ci*COUT + co)*K + (K-1-k)]
                : w[((size_t)co*CIN + ci)*K + k];
}

// ---------------- generic fused conv kernel ----------------
// EPI: 0=bias only ([b][co][t]), 1=LN+LeakyReLU, 2=LN+GLU (writes COUT/2 ch),
//      3=VQ argmin (bias=||c||^2, writes int idx), 4=bias only transposed ([b][t][co])
template<int CIN1,int CIN2,int COUT,int KS,int CI_BLK,int G_CO,int TPT,int EPI>
__global__ __launch_bounds__(256,2) void conv_k(
    const float* __restrict__ in1, const float* __restrict__ in2,
    const float* __restrict__ wt, const float* __restrict__ bias,
    const float* __restrict__ gamma, const float* __restrict__ beta,
    float* __restrict__ out, int* __restrict__ oidx)
{
    constexpr int CIN  = CIN1 + CIN2;
    constexpr int PAD  = (KS - 1) / 2;
    constexpr int G_T  = 256 / G_CO;
    constexpr int TT   = G_T * TPT;
    constexpr int CPT  = COUT / G_CO;
    constexpr int RIN  = TPT + KS - 1;
    constexpr int IROW = TT + KS - 1;
    constexpr int WELEMS = CI_BLK * KS * COUT;
    constexpr int IELEMS = CI_BLK * IROW;
    constexpr int NCB  = CIN / CI_BLK;
    constexpr bool NEED_RED = (EPI==1 || EPI==2 || EPI==3);
    constexpr int RSTRIDE = G_CO + 1;

    extern __shared__ float smem[];
    float* sW = smem;
    float* sI = sW + WELEMS;
    float* sRa = sI + IELEMS;                 // TT*RSTRIDE
    float* sRb = sRa + (NEED_RED ? TT*RSTRIDE : 0);
    float* sMean = sRb + (NEED_RED ? TT*RSTRIDE : 0);
    float* sRstd = sMean + (NEED_RED ? TT : 0);

    const int tid = threadIdx.x;
    const int cg  = tid % G_CO;
    const int tg  = tid / G_CO;
    const int b   = blockIdx.y;
    const int t0  = blockIdx.x * TT;

    float acc[CPT][TPT];
    #pragma unroll
    for (int i = 0; i < CPT; i++)
        #pragma unroll
        for (int t = 0; t < TPT; t++) acc[i][t] = 0.f;

    for (int cb = 0; cb < NCB; cb++) {
        __syncthreads();
        const float* wsrc = wt + (size_t)cb * WELEMS;
        for (int e = tid; e < WELEMS; e += 256) sW[e] = wsrc[e];
        for (int e = tid; e < IELEMS; e += 256) {
            int ci = e / IROW, j = e % IROW;
            int t  = t0 - PAD + j;
            int cig = cb*CI_BLK + ci;
            float v = 0.f;
            if (t >= 0 && t < T_LEN) {
                if (CIN2 == 0 || cig < CIN1)
                    v = in1[((size_t)b*CIN1 + cig)*T_LEN + t];
                else
                    v = in2[((size_t)b*CIN2 + (cig - CIN1))*T_LEN + t];
            }
            sI[e] = v;
        }
        __syncthreads();

        #pragma unroll 1
        for (int ci = 0; ci < CI_BLK; ci++) {
            float rin[RIN];
            #pragma unroll
            for (int j = 0; j < RIN; j++) rin[j] = sI[ci*IROW + tg*TPT + j];
            #pragma unroll
            for (int k = 0; k < KS; k++) {
                #pragma unroll
                for (int i = 0; i < CPT; i++) {
                    float wv = sW[(ci*KS + k)*COUT + cg + G_CO*i];
                    #pragma unroll
                    for (int t = 0; t < TPT; t++)
                        acc[i][t] = fmaf(wv, rin[t + k], acc[i][t]);
                }
            }
        }
    }

    if constexpr (EPI == 3) {
        // VQ argmin: score = ||c||^2 - 2 * (z . c)
        float bv[CPT];
        #pragma unroll
        for (int i = 0; i < CPT; i++) bv[i] = bias[cg + G_CO*i];
        int* sRi = (int*)sRb;
        #pragma unroll
        for (int t = 0; t < TPT; t++) {
            float best = 3.4e38f; int bi = 0;
            #pragma unroll
            for (int i = 0; i < CPT; i++) {
                float v = bv[i] - 2.f*acc[i][t];
                int ii = cg + G_CO*i;
                if (v < best || (v == best && ii < bi)) { best = v; bi = ii; }
            }
            int tl = tg*TPT + t;
            sRa[tl*RSTRIDE + cg] = best;
            sRi[tl*RSTRIDE + cg] = bi;
        }
        __syncthreads();
        if (tid < TT) {
            float best = 3.4e38f; int bi = 0;
            for (int g = 0; g < G_CO; g++) {
                float v = sRa[tid*RSTRIDE + g]; int ii = sRi[tid*RSTRIDE + g];
                if (v < best || (v == best && ii < bi)) { best = v; bi = ii; }
            }
            oidx[(size_t)b*T_LEN + t0 + tid] = bi;
        }
        return;
    } else {
        // add conv bias
        #pragma unroll
        for (int i = 0; i < CPT; i++) {
            float bv = bias[cg + G_CO*i];
            #pragma unroll
            for (int t = 0; t < TPT; t++) acc[i][t] += bv;
        }

        if constexpr (EPI == 1 || EPI == 2) {
            #pragma unroll
            for (int t = 0; t < TPT; t++) {
                float s = 0.f, q = 0.f;
                #pragma unroll
                for (int i = 0; i < CPT; i++) { float v = acc[i][t]; s += v; q += v*v; }
                int tl = tg*TPT + t;
                sRa[tl*RSTRIDE + cg] = s;
                sRb[tl*RSTRIDE + cg] = q;
            }
            __syncthreads();
            if (tid < TT) {
                float s = 0.f, q = 0.f;
                for (int g = 0; g < G_CO; g++) { s += sRa[tid*RSTRIDE + g]; q += sRb[tid*RSTRIDE + g]; }
                float m = s * (1.f/COUT);
                float v = q * (1.f/COUT) - m*m;
                sMean[tid] = m;
                sRstd[tid] = rsqrtf(v + 1e-5f);
            }
            __syncthreads();

            if constexpr (EPI == 1) {
                #pragma unroll
                for (int i = 0; i < CPT; i++) {
                    int co = cg + G_CO*i;
                    float ga = gamma[co], be = beta[co];
                    #pragma unroll
                    for (int t = 0; t < TPT; t++) {
                        int tl = tg*TPT + t;
                        float v = (acc[i][t] - sMean[tl]) * sRstd[tl] * ga + be;
                        v = v > 0.f ? v : 0.2f*v;
                        out[((size_t)b*COUT + co)*T_LEN + t0 + tl] = v;
                    }
                }
            } else { // GLU
                constexpr int H = CPT/2;
                #pragma unroll
                for (int i = 0; i < H; i++) {
                    int co = cg + G_CO*i;
                    int co2 = co + COUT/2;
                    float ga = gamma[co], be = beta[co];
                    float g2a = gamma[co2], b2 = beta[co2];
                    #pragma unroll
                    for (int t = 0; t < TPT; t++) {
                        int tl = tg*TPT + t;
                        float m = sMean[tl], r = sRstd[tl];
                        float a  = (acc[i][t]   - m) * r * ga  + be;
                        float gt = (acc[i+H][t] - m) * r * g2a + b2;
                        out[((size_t)b*(COUT/2) + co)*T_LEN + t0 + tl] = a * (1.f/(1.f + expf(-gt)));
                    }
                }
            }
        } else if constexpr (EPI == 0) {
            #pragma unroll
            for (int i = 0; i < CPT; i++) {
                int co = cg + G_CO*i;
                #pragma unroll
                for (int t = 0; t < TPT; t++)
                    out[((size_t)b*COUT + co)*T_LEN + t0 + tg*TPT + t] = acc[i][t];
            }
        } else { // EPI == 4, transposed write [b][t][co]
            #pragma unroll
            for (int i = 0; i < CPT; i++) {
                int co = cg + G_CO*i;
                #pragma unroll
                for (int t = 0; t < TPT; t++) {
                    int tl = tg*TPT + t;
                    out[((size_t)b*T_LEN + t0 + tl)*COUT + co] = acc[i][t];
                }
            }
        }
    }
}

// ---------------- host launch helper ----------------
#define LAUNCH_CONV(CIN1,CIN2,COUT,KS,CIB,GCO,TPT,EPI, in1,in2,wtp,biasp,gap,bep,outp,oidxp) do { \
    constexpr int GT_ = 256/(GCO); constexpr int TT_ = GT_*(TPT); \
    constexpr int WE_ = (CIB)*(KS)*(COUT); \
    constexpr int IE_ = (CIB)*(TT_+(KS)-1); \
    constexpr int RED_ = ((EPI)==1||(EPI)==2||(EPI)==3) ? (2*TT_*((GCO)+1) + 2*TT_) : 0; \
    constexpr int SB_ = (WE_+IE_+RED_)*4; \
    auto kf_ = &conv_k<CIN1,CIN2,COUT,KS,CIB,GCO,TPT,EPI>; \
    if (SB_ > 48*1024) cudaFuncSetAttribute(kf_, cudaFuncAttributeMaxDynamicSharedMemorySize, SB_); \
    kf_<<<dim3(T_LEN/TT_, B_SZ), 256, SB_>>>(in1,in2,wtp,biasp,gap,bep,outp,oidxp); \
} while (0)

extern "C" void kernel_launch(void* const* d_in, const int* in_sizes, int n_in,
                              void* d_out, int out_size) {
    (void)in_sizes; (void)n_in; (void)out_size;
    const float* x       = (const float*)d_in[0];
    const int*   y       = (const int*)  d_in[1];
    const float* enc_w1  = (const float*)d_in[2];
    const float* enc_b1  = (const float*)d_in[3];
    const float* enc_g1  = (const float*)d_in[4];
    const float* enc_bt1 = (const float*)d_in[5];
    const float* enc_w2  = (const float*)d_in[6];
    const float* enc_b2  = (const float*)d_in[7];
    const float* enc_g2  = (const float*)d_in[8];
    const float* enc_bt2 = (const float*)d_in[9];
    const float* enc_w3  = (const float*)d_in[10];
    const float* enc_b3  = (const float*)d_in[11];
    const float* enc_g3  = (const float*)d_in[12];
    const float* enc_bt3 = (const float*)d_in[13];
    const float* mlp_w   = (const float*)d_in[14];
    const float* mlp_b   = (const float*)d_in[15];
    const float* codebook= (const float*)d_in[16];
    const float* spk_emb = (const float*)d_in[17];
    const float* dec_w1  = (const float*)d_in[18];
    const float* dec_b1  = (const float*)d_in[19];
    const float* dec_g1  = (const float*)d_in[20];
    const float* dec_bt1 = (const float*)d_in[21];
    const float* dec_w2  = (const float*)d_in[22];
    const float* dec_b2  = (const float*)d_in[23];
    const float* dec_g2  = (const float*)d_in[24];
    const float* dec_bt2 = (const float*)d_in[25];
    const float* dec_w3  = (const float*)d_in[26];
    const float* dec_b3  = (const float*)d_in[27];
    float* outp = (float*)d_out;

    float *bufA, *bufB, *ye, *z, *zvq, *wt, *cbt, *cbn, *spk; int* idx;
    cudaGetSymbolAddress((void**)&bufA, g_bufA);
    cudaGetSymbolAddress((void**)&bufB, g_bufB);
    cudaGetSymbolAddress((void**)&ye,   g_ye);
    cudaGetSymbolAddress((void**)&z,    g_z);
    cudaGetSymbolAddress((void**)&zvq,  g_zvq);
    cudaGetSymbolAddress((void**)&wt,   g_wt);
    cudaGetSymbolAddress((void**)&cbt,  g_cbt);
    cudaGetSymbolAddress((void**)&cbn,  g_cbn);
    cudaGetSymbolAddress((void**)&spk,  g_spk);
    cudaGetSymbolAddress((void**)&idx,  g_idx);

    // x [B,T,F] -> [B,F,T]
    transpose_x_k<<<dim3(T_LEN/32, 3, B_SZ), dim3(32,8)>>>(x, bufA);
    // speaker embedding: normalize + gather
    spknorm_k<<<128, 128>>>(spk_emb, spk);
    ye_gather_k<<<dim3(T_LEN/32, B_SZ), 256>>>(y, spk, ye);

    // encoder 1: 80 -> 512, LN + LeakyReLU
    wtrans_k<<<(512*80*5 + 255)/256, 256>>>(enc_w1, wt, 80, 512, 5, 0);
    LAUNCH_CONV(80,0,512,5, 8,64,8, 1, bufA, (const float*)nullptr, wt, enc_b1, enc_g1, enc_bt1, bufB, (int*)nullptr);
    // encoder 2
    wtrans_k<<<(512*512*5 + 255)/256, 256>>>(enc_w2, wt, 512, 512, 5, 0);
    LAUNCH_CONV(512,0,512,5, 8,64,8, 1, bufB, (const float*)nullptr, wt, enc_b2, enc_g2, enc_bt2, bufA, (int*)nullptr);
    // encoder 3
    wtrans_k<<<(512*512*5 + 255)/256, 256>>>(enc_w3, wt, 512, 512, 5, 0);
    LAUNCH_CONV(512,0,512,5, 8,64,8, 1, bufA, (const float*)nullptr, wt, enc_b3, enc_g3, enc_bt3, bufB, (int*)nullptr);
    // mlp 1x1: 512 -> 64
    wtrans_k<<<(512*64 + 255)/256, 256>>>(mlp_w, wt, 512, 64, 1, 0);
    LAUNCH_CONV(512,0,64,1, 16,32,8, 0, bufB, (const float*)nullptr, wt, mlp_b, (const float*)nullptr, (const float*)nullptr, z, (int*)nullptr);
    // VQ: argmin over 512 codes
    wtrans_k<<<(64*512 + 255)/256, 256>>>(codebook, cbt, 64, 512, 1, 0);
    cbnorm_k<<<4, 128>>>(codebook, cbn);
    LAUNCH_CONV(64,0,512,1, 16,64,8, 3, z, (const float*)nullptr, cbt, cbn, (const float*)nullptr, (const float*)nullptr, (float*)nullptr, idx);
    zvq_gather_k<<<dim3(T_LEN/32, B_SZ), 256>>>(idx, codebook, zvq);
    // decoder 1: (64 + 128) -> 1024, LN + GLU -> 512
    wtrans_k<<<(192*1024*5 + 255)/256, 256>>>(dec_w1, wt, 192, 1024, 5, 1);
    LAUNCH_CONV(64,128,1024,5, 4,128,8, 2, zvq, ye, wt, dec_b1, dec_g1, dec_bt1, bufA, (int*)nullptr);
    // decoder 2: (512 + 128) -> 1024, LN + GLU -> 512
    wtrans_k<<<(640*1024*5 + 255)/256, 256>>>(dec_w2, wt, 640, 1024, 5, 1);
    LAUNCH_CONV(512,128,1024,5, 4,128,8, 2, bufA, ye, wt, dec_b2, dec_g2, dec_bt2, bufB, (int*)nullptr);
    // decoder 3: (512 + 128) -> 80, transposed write to [B,T,F]
    wtrans_k<<<(640*80*5 + 255)/256, 256>>>(dec_w3, wt, 640, 80, 5, 1);
    LAUNCH_CONV(512,128,80,5, 8,16,4, 4, bufB, ye, wt, dec_b3, (const float*)nullptr, (const float*)nullptr, outp, (int*)nullptr);
}

// round 4
// speedup vs baseline: 1.5320x; 1.0008x over previous
#include <cuda_runtime.h>
#include <math.h>

#define T_LEN 4096
#define B_SZ  16

// ---------------- scratch (device globals; no allocation allowed) ----------------
__device__ float g_bufA[16*512*4096];
__device__ float g_bufB[16*512*4096];
__device__ float g_ye  [16*128*4096];
__device__ float g_z   [16*64*4096];
__device__ float g_zvq [16*64*4096];
__device__ float g_wt  [640*5*1024];
__device__ float g_cbt [64*512];
__device__ float g_cbn [512];
__device__ float g_spk [128*128];
__device__ int   g_idx [16*4096];

// ---------------- small helper kernels ----------------
__global__ void transpose_x_k(const float* __restrict__ x, float* __restrict__ xt) {
    __shared__ float tile[32][33];
    int b = blockIdx.z;
    int t0 = blockIdx.x*32, f0 = blockIdx.y*32;
    int tx = threadIdx.x, ty = threadIdx.y;
    for (int j = ty; j < 32; j += 8) {
        int t = t0 + j, f = f0 + tx;
        tile[j][tx] = (f < 80) ? x[((size_t)b*T_LEN + t)*80 + f] : 0.f;
    }
    __syncthreads();
    for (int j = ty; j < 32; j += 8) {
        int f = f0 + j, t = t0 + tx;
        if (f < 80) xt[((size_t)b*80 + f)*T_LEN + t] = tile[tx][j];
    }
}

__global__ void spknorm_k(const float* __restrict__ spk, float* __restrict__ o) {
    __shared__ float red[128];
    int r = blockIdx.x, t = threadIdx.x;
    float v = spk[r*128 + t];
    red[t] = v*v;
    __syncthreads();
    for (int s = 64; s > 0; s >>= 1) { if (t < s) red[t] += red[t+s]; __syncthreads(); }
    o[r*128 + t] = v * rsqrtf(red[0]);
}

__global__ void cbnorm_k(const float* __restrict__ cb, float* __restrict__ n) {
    int c = blockIdx.x*128 + threadIdx.x;
    if (c < 512) {
        float s = 0.f;
        for (int d = 0; d < 64; d++) { float v = cb[c*64 + d]; s += v*v; }
        n[c] = s;
    }
}

__global__ void ye_gather_k(const int* __restrict__ y, const float* __restrict__ spk,
                            float* __restrict__ ye) {
    int b = blockIdx.y;
    int t = blockIdx.x*32 + (threadIdx.x & 31);
    int w = threadIdx.x >> 5;
    int yi = y[(size_t)b*T_LEN + t];
    for (int c = w; c < 128; c += 8)
        ye[((size_t)b*128 + c)*T_LEN + t] = spk[yi*128 + c];
}

__global__ void zvq_gather_k(const int* __restrict__ idx, const float* __restrict__ cb,
                             float* __restrict__ zvq) {
    int b = blockIdx.y;
    int t = blockIdx.x*32 + (threadIdx.x & 31);
    int w = threadIdx.x >> 5;
    int ii = idx[(size_t)b*T_LEN + t];
    for (int d = w; d < 64; d += 8)
        zvq[((size_t)b*64 + d)*T_LEN + t] = cb[ii*64 + d];
}

// weight transform -> wt[ci][k][co] contiguous (dec=1 also does ConvT flip/transpose)
__global__ void wtrans_k(const float* __restrict__ w, float* __restrict__ wt,
                         int CIN, int COUT, int K, int dec) {
    int e = blockIdx.x*256 + threadIdx.x;
    int total = CIN*COUT*K;
    if (e >= total) return;
    int co = e % COUT; int r = e / COUT; int k = r % K; int ci = r / K;
    wt[e] = dec ? w[((size_t)ci*COUT + co)*K + (K-1-k)]
                : w[((size_t)co*CIN + ci)*K + k];
}

// ---------------- generic fused conv kernel ----------------
// EPI: 0=bias only ([b][co][t]), 1=LN+LeakyReLU, 2=LN+GLU (writes COUT/2 ch),
//      3=VQ argmin (bias=||c||^2, writes int idx), 4=bias only transposed ([b][t][co])
template<int CIN1,int CIN2,int COUT,int KS,int CI_BLK,int G_CO,int TPT,int EPI>
__global__ __launch_bounds__(256,2) void conv_k(
    const float* __restrict__ in1, const float* __restrict__ in2,
    const float* __restrict__ wt, const float* __restrict__ bias,
    const float* __restrict__ gamma, const float* __restrict__ beta,
    float* __restrict__ out, int* __restrict__ oidx)
{
    constexpr int CIN  = CIN1 + CIN2;
    constexpr int PAD  = (KS - 1) / 2;
    constexpr int G_T  = 256 / G_CO;
    constexpr int TT   = G_T * TPT;
    constexpr int CPT  = COUT / G_CO;
    constexpr int RIN  = TPT + KS - 1;
    constexpr int IROW = TT + KS - 1;
    constexpr int WELEMS = CI_BLK * KS * COUT;
    constexpr int IELEMS = CI_BLK * IROW;
    constexpr int NCB  = CIN / CI_BLK;
    constexpr bool NEED_RED = (EPI==1 || EPI==2 || EPI==3);
    constexpr int RSTRIDE = G_CO + 1;

    extern __shared__ float smem[];
    float* sW = smem;
    float* sI = sW + WELEMS;
    float* sRa = sI + IELEMS;                 // TT*RSTRIDE
    float* sRb = sRa + (NEED_RED ? TT*RSTRIDE : 0);
    float* sMean = sRb + (NEED_RED ? TT*RSTRIDE : 0);
    float* sRstd = sMean + (NEED_RED ? TT : 0);

    const int tid = threadIdx.x;
    const int cg  = tid % G_CO;
    const int tg  = tid / G_CO;
    const int b   = blockIdx.y;
    const int t0  = blockIdx.x * TT;

    float acc[CPT][TPT];
    #pragma unroll
    for (int i = 0; i < CPT; i++)
        #pragma unroll
        for (int t = 0; t < TPT; t++) acc[i][t] = 0.f;

    for (int cb = 0; cb < NCB; cb++) {
        __syncthreads();
        const float* wsrc = wt + (size_t)cb * WELEMS;
        for (int e = tid; e < WELEMS; e += 256) sW[e] = wsrc[e];
        for (int e = tid; e < IELEMS; e += 256) {
            int ci = e / IROW, j = e % IROW;
            int t  = t0 - PAD + j;
            int cig = cb*CI_BLK + ci;
            float v = 0.f;
            if (t >= 0 && t < T_LEN) {
                if (CIN2 == 0 || cig < CIN1)
                    v = in1[((size_t)b*CIN1 + cig)*T_LEN + t];
                else
                    v = in2[((size_t)b*CIN2 + (cig - CIN1))*T_LEN + t];
            }
            sI[e] = v;
        }
        __syncthreads();

        #pragma unroll 1
        for (int ci = 0; ci < CI_BLK; ci++) {
            float rin[RIN];
            #pragma unroll
            for (int j = 0; j < RIN; j++) rin[j] = sI[ci*IROW + tg*TPT + j];
            #pragma unroll
            for (int k = 0; k < KS; k++) {
                #pragma unroll
                for (int i = 0; i < CPT; i++) {
                    float wv = sW[(ci*KS + k)*COUT + cg + G_CO*i];
                    #pragma unroll
                    for (int t = 0; t < TPT; t++)
                        acc[i][t] = fmaf(wv, rin[t + k], acc[i][t]);
                }
            }
        }
    }

    if constexpr (EPI == 3) {
        // VQ argmin: score = ||c||^2 - 2 * (z . c)
        float bv[CPT];
        #pragma unroll
        for (int i = 0; i < CPT; i++) bv[i] = bias[cg + G_CO*i];
        int* sRi = (int*)sRb;
        #pragma unroll
        for (int t = 0; t < TPT; t++) {
            float best = 3.4e38f; int bi = 0;
            #pragma unroll
            for (int i = 0; i < CPT; i++) {
                float v = bv[i] - 2.f*acc[i][t];
                int ii = cg + G_CO*i;
                if (v < best || (v == best && ii < bi)) { best = v; bi = ii; }
            }
            int tl = tg*TPT + t;
            sRa[tl*RSTRIDE + cg] = best;
            sRi[tl*RSTRIDE + cg] = bi;
        }
        __syncthreads();
        if (tid < TT) {
            float best = 3.4e38f; int bi = 0;
            for (int g = 0; g < G_CO; g++) {
                float v = sRa[tid*RSTRIDE + g]; int ii = sRi[tid*RSTRIDE + g];
                if (v < best || (v == best && ii < bi)) { best = v; bi = ii; }
            }
            oidx[(size_t)b*T_LEN + t0 + tid] = bi;
        }
        return;
    } else {
        // add conv bias
        #pragma unroll
        for (int i = 0; i < CPT; i++) {
            float bv = bias[cg + G_CO*i];
            #pragma unroll
            for (int t = 0; t < TPT; t++) acc[i][t] += bv;
        }

        if constexpr (EPI == 1 || EPI == 2) {
            #pragma unroll
            for (int t = 0; t < TPT; t++) {
                float s = 0.f, q = 0.f;
                #pragma unroll
                for (int i = 0; i < CPT; i++) { float v = acc[i][t]; s += v; q += v*v; }
                int tl = tg*TPT + t;
                sRa[tl*RSTRIDE + cg] = s;
                sRb[tl*RSTRIDE + cg] = q;
            }
            __syncthreads();
            if (tid < TT) {
                float s = 0.f, q = 0.f;
                for (int g = 0; g < G_CO; g++) { s += sRa[tid*RSTRIDE + g]; q += sRb[tid*RSTRIDE + g]; }
                float m = s * (1.f/COUT);
                float v = q * (1.f/COUT) - m*m;
                sMean[tid] = m;
                sRstd[tid] = rsqrtf(v + 1e-5f);
            }
            __syncthreads();

            if constexpr (EPI == 1) {
                #pragma unroll
                for (int i = 0; i < CPT; i++) {
                    int co = cg + G_CO*i;
                    float ga = gamma[co], be = beta[co];
                    #pragma unroll
                    for (int t = 0; t < TPT; t++) {
                        int tl = tg*TPT + t;
                        float v = (acc[i][t] - sMean[tl]) * sRstd[tl] * ga + be;
                        v = v > 0.f ? v : 0.2f*v;
                        out[((size_t)b*COUT + co)*T_LEN + t0 + tl] = v;
                    }
                }
            } else { // GLU
                constexpr int H = CPT/2;
                #pragma unroll
                for (int i = 0; i < H; i++) {
                    int co = cg + G_CO*i;
                    int co2 = co + COUT/2;
                    float ga = gamma[co], be = beta[co];
                    float g2a = gamma[co2], b2 = beta[co2];
                    #pragma unroll
                    for (int t = 0; t < TPT; t++) {
                        int tl = tg*TPT + t;
                        float m = sMean[tl], r = sRstd[tl];
                        float a  = (acc[i][t]   - m) * r * ga  + be;
                        float gt = (acc[i+H][t] - m) * r * g2a + b2;
                        out[((size_t)b*(COUT/2) + co)*T_LEN + t0 + tl] = a * (1.f/(1.f + expf(-gt)));
                    }
                }
            }
        } else if constexpr (EPI == 0) {
            #pragma unroll
            for (int i = 0; i < CPT; i++) {
                int co = cg + G_CO*i;
                #pragma unroll
                for (int t = 0; t < TPT; t++)
                    out[((size_t)b*COUT + co)*T_LEN + t0 + tg*TPT + t] = acc[i][t];
            }
        } else { // EPI == 4, transposed write [b][t][co]
            #pragma unroll
            for (int i = 0; i < CPT; i++) {
                int co = cg + G_CO*i;
                #pragma unroll
                for (int t = 0; t < TPT; t++) {
                    int tl = tg*TPT + t;
                    out[((size_t)b*T_LEN + t0 + tl)*COUT + co] = acc[i][t];
                }
            }
        }
    }
}

// ---------------- host launch helper ----------------
#define LAUNCH_CONV(CIN1,CIN2,COUT,KS,CIB,GCO,TPT,EPI, in1,in2,wtp,biasp,gap,bep,outp,oidxp) do { \
    constexpr int GT_ = 256/(GCO); constexpr int TT_ = GT_*(TPT); \
    constexpr int WE_ = (CIB)*(KS)*(COUT); \
    constexpr int IE_ = (CIB)*(TT_+(KS)-1); \
    constexpr int RED_ = ((EPI)==1||(EPI)==2||(EPI)==3) ? (2*TT_*((GCO)+1) + 2*TT_) : 0; \
    constexpr int SB_ = (WE_+IE_+RED_)*4; \
    auto kf_ = &conv_k<CIN1,CIN2,COUT,KS,CIB,GCO,TPT,EPI>; \
    if (SB_ > 48*1024) cudaFuncSetAttribute(kf_, cudaFuncAttributeMaxDynamicSharedMemorySize, SB_); \
    kf_<<<dim3(T_LEN/TT_, B_SZ), 256, SB_>>>(in1,in2,wtp,biasp,gap,bep,outp,oidxp); \
} while (0)

extern "C" void kernel_launch(void* const* d_in, const int* in_sizes, int n_in,
                              void* d_out, int out_size) {
    (void)in_sizes; (void)n_in; (void)out_size;
    const float* x       = (const float*)d_in[0];
    const int*   y       = (const int*)  d_in[1];
    const float* enc_w1  = (const float*)d_in[2];
    const float* enc_b1  = (const float*)d_in[3];
    const float* enc_g1  = (const float*)d_in[4];
    const float* enc_bt1 = (const float*)d_in[5];
    const float* enc_w2  = (const float*)d_in[6];
    const float* enc_b2  = (const float*)d_in[7];
    const float* enc_g2  = (const float*)d_in[8];
    const float* enc_bt2 = (const float*)d_in[9];
    const float* enc_w3  = (const float*)d_in[10];
    const float* enc_b3  = (const float*)d_in[11];
    const float* enc_g3  = (const float*)d_in[12];
    const float* enc_bt3 = (const float*)d_in[13];
    const float* mlp_w   = (const float*)d_in[14];
    const float* mlp_b   = (const float*)d_in[15];
    const float* codebook= (const float*)d_in[16];
    const float* spk_emb = (const float*)d_in[17];
    const float* dec_w1  = (const float*)d_in[18];
    const float* dec_b1  = (const float*)d_in[19];
    const float* dec_g1  = (const float*)d_in[20];
    const float* dec_bt1 = (const float*)d_in[21];
    const float* dec_w2  = (const float*)d_in[22];
    const float* dec_b2  = (const float*)d_in[23];
    const float* dec_g2  = (const float*)d_in[24];
    const float* dec_bt2 = (const float*)d_in[25];
    const float* dec_w3  = (const float*)d_in[26];
    const float* dec_b3  = (const float*)d_in[27];
    float* outp = (float*)d_out;

    float *bufA, *bufB, *ye, *z, *zvq, *wt, *cbt, *cbn, *spk; int* idx;
    cudaGetSymbolAddress((void**)&bufA, g_bufA);
    cudaGetSymbolAddress((void**)&bufB, g_bufB);
    cudaGetSymbolAddress((void**)&ye,   g_ye);
    cudaGetSymbolAddress((void**)&z,    g_z);
    cudaGetSymbolAddress((void**)&zvq,  g_zvq);
    cudaGetSymbolAddress((void**)&wt,   g_wt);
    cudaGetSymbolAddress((void**)&cbt,  g_cbt);
    cudaGetSymbolAddress((void**)&cbn,  g_cbn);
    cudaGetSymbolAddress((void**)&spk,  g_spk);
    cudaGetSymbolAddress((void**)&idx,  g_idx);

    // x [B,T,F] -> [B,F,T]
    transpose_x_k<<<dim3(T_LEN/32, 3, B_SZ), dim3(32,8)>>>(x, bufA);
    // speaker embedding: normalize + gather
    spknorm_k<<<128, 128>>>(spk_emb, spk);
    ye_gather_k<<<dim3(T_LEN/32, B_SZ), 256>>>(y, spk, ye);

    // encoder 1: 80 -> 512, LN + LeakyReLU
    wtrans_k<<<(512*80*5 + 255)/256, 256>>>(enc_w1, wt, 80, 512, 5, 0);
    LAUNCH_CONV(80,0,512,5, 8,64,8, 1, bufA, (const float*)nullptr, wt, enc_b1, enc_g1, enc_bt1, bufB, (int*)nullptr);
    // encoder 2
    wtrans_k<<<(512*512*5 + 255)/256, 256>>>(enc_w2, wt, 512, 512, 5, 0);
    LAUNCH_CONV(512,0,512,5, 8,64,8, 1, bufB, (const float*)nullptr, wt, enc_b2, enc_g2, enc_bt2, bufA, (int*)nullptr);
    // encoder 3
    wtrans_k<<<(512*512*5 + 255)/256, 256>>>(enc_w3, wt, 512, 512, 5, 0);
    LAUNCH_CONV(512,0,512,5, 8,64,8, 1, bufA, (const float*)nullptr, wt, enc_b3, enc_g3, enc_bt3, bufB, (int*)nullptr);
    // mlp 1x1: 512 -> 64
    wtrans_k<<<(512*64 + 255)/256, 256>>>(mlp_w, wt, 512, 64, 1, 0);
    LAUNCH_CONV(512,0,64,1, 16,32,8, 0, bufB, (const float*)nullptr, wt, mlp_b, (const float*)nullptr, (const float*)nullptr, z, (int*)nullptr);
    // VQ: argmin over 512 codes
    wtrans_k<<<(64*512 + 255)/256, 256>>>(codebook, cbt, 64, 512, 1, 0);
    cbnorm_k<<<4, 128>>>(codebook, cbn);
    LAUNCH_CONV(64,0,512,1, 16,64,8, 3, z, (const float*)nullptr, cbt, cbn, (const float*)nullptr, (const float*)nullptr, (float*)nullptr, idx);
    zvq_gather_k<<<dim3(T_LEN/32, B_SZ), 256>>>(idx, codebook, zvq);
    // decoder 1: (64 + 128) -> 1024, LN + GLU -> 512
    wtrans_k<<<(192*1024*5 + 255)/256, 256>>>(dec_w1, wt, 192, 1024, 5, 1);
    LAUNCH_CONV(64,128,1024,5, 4,128,8, 2, zvq, ye, wt, dec_b1, dec_g1, dec_bt1, bufA, (int*)nullptr);
    // decoder 2: (512 + 128) -> 1024, LN + GLU -> 512
    wtrans_k<<<(640*1024*5 + 255)/256, 256>>>(dec_w2, wt, 640, 1024, 5, 1);
    LAUNCH_CONV(512,128,1024,5, 4,128,8, 2, bufA, ye, wt, dec_b2, dec_g2, dec_bt2, bufB, (int*)nullptr);
    // decoder 3: (512 + 128) -> 80, transposed write to [B,T,F]
    wtrans_k<<<(640*80*5 + 255)/256, 256>>>(dec_w3, wt, 640, 80, 5, 1);
    LAUNCH_CONV(512,128,80,5, 8,16,4, 4, bufB, ye, wt, dec_b3, (const float*)nullptr, (const float*)nullptr, outp, (int*)nullptr);
}

// round 8
// speedup vs baseline: 6.0205x; 3.9298x over previous
#include <cuda_runtime.h>
#include <cuda_bf16.h>
#include <math.h>
#include <stdint.h>

#define T_LEN 4096
#define B_SZ  16

// ---------------- scratch ----------------
__device__ float          g_raw  [16ll*1024*4096];
__device__ float          g_act32[16ll*512*4096];
__device__ float          g_z    [16ll*64*4096];
__device__ __nv_bfloat16  g_hAh[16ll*4096*512], g_hAl[16ll*4096*512];
__device__ __nv_bfloat16  g_hBh[16ll*4096*512], g_hBl[16ll*4096*512];
__device__ __nv_bfloat16  g_xh [16ll*4096*128], g_xl [16ll*4096*128];
__device__ __nv_bfloat16  g_yeh[16ll*4096*128], g_yel[16ll*4096*128];
__device__ __nv_bfloat16  g_zvh[16ll*4096*64],  g_zvl[16ll*4096*64];
__device__ __nv_bfloat16  g_wh [5ll*1024*640],  g_wl [5ll*1024*640];
__device__ float          g_wt [512*64];
__device__ float          g_cbt[64*512];
__device__ float          g_cbn[512];
__device__ float          g_spk[128*128];
__device__ int            g_idx[16*4096];

// ---------------- PTX helpers (sm_80-era, valid on base sm_103 target) ----------------
__device__ __forceinline__ uint32_t s32(const void* p) {
    uint32_t a;
    asm("{ .reg .u64 t; cvta.to.shared.u64 t, %1; cvt.u32.u64 %0, t; }" : "=r"(a) : "l"(p));
    return a;
}
__device__ __forceinline__ void cpa16(uint32_t d, const void* s, bool v) {
    int sz = v ? 16 : 0;
    asm volatile("cp.async.cg.shared.global [%0], [%1], 16, %2;" :: "r"(d), "l"(s), "r"(sz) : "memory");
}
#define CP_COMMIT() asm volatile("cp.async.commit_group;" ::: "memory")
__device__ __forceinline__ void ldsm4(uint32_t* r, uint32_t a) {
    asm volatile("ldmatrix.sync.aligned.m8n8.x4.shared.b16 {%0,%1,%2,%3}, [%4];"
                 : "=r"(r[0]),"=r"(r[1]),"=r"(r[2]),"=r"(r[3]) : "r"(a));
}
__device__ __forceinline__ void ldsm2(uint32_t* r, uint32_t a) {
    asm volatile("ldmatrix.sync.aligned.m8n8.x2.shared.b16 {%0,%1}, [%2];"
                 : "=r"(r[0]),"=r"(r[1]) : "r"(a));
}
__device__ __forceinline__ void mma16816(float* d, const uint32_t* a, const uint32_t* b) {
    asm volatile("mma.sync.aligned.m16n8k16.row.col.f32.bf16.bf16.f32 "
                 "{%0,%1,%2,%3}, {%4,%5,%6,%7}, {%8,%9}, {%0,%1,%2,%3};"
                 : "+f"(d[0]), "+f"(d[1]), "+f"(d[2]), "+f"(d[3])
                 : "r"(a[0]), "r"(a[1]), "r"(a[2]), "r"(a[3]), "r"(b[0]), "r"(b[1]));
}

// ---------------- mma.sync K=5 implicit conv GEMM ----------------
// grid (T/128, B, COUTP/128), block 256 (8 warps, warp tile 64co x 32t).
// smem: B bufs 2x(132 rows x 80B x {hi,lo}), A bufs 2x(128 rows x 80B x {hi,lo})
template<int CINP>
__global__ void __launch_bounds__(256,2) gemm5_k(
    const __nv_bfloat16* __restrict__ in1h, const __nv_bfloat16* __restrict__ in1l, int C1,
    const __nv_bfloat16* __restrict__ in2h, const __nv_bfloat16* __restrict__ in2l,
    const __nv_bfloat16* __restrict__ wh,   const __nv_bfloat16* __restrict__ wl,
    const float* __restrict__ bias, int COUT, int COUTP,
    float* __restrict__ raw)
{
    constexpr int NCH  = CINP / 32;
    constexpr int ITER = NCH * 5;
    extern __shared__ char sm[];
    const uint32_t sb = s32(sm);
    const uint32_t B_OFF0 = 0u, B_OFF1 = 21120u;     // each: hi 10560 + lo 10560
    const uint32_t A_OFF0 = 42240u, A_OFF1 = 62720u; // each: hi 10240 + lo 10240

    const int tid = threadIdx.x, lane = tid & 31, wid = tid >> 5;
    const int mw = wid & 1, nw = wid >> 1;
    const int t0 = blockIdx.x * 128, b = blockIdx.y, mo = blockIdx.z;

    float acc[4][4][4];
    #pragma unroll
    for (int i = 0; i < 4; i++)
        #pragma unroll
        for (int j = 0; j < 4; j++)
            #pragma unroll
            for (int q = 0; q < 4; q++) acc[i][j][q] = 0.f;

    // lane-level ldmatrix addressing
    const uint32_t aRow = (uint32_t)(((lane >> 3) & 1) * 8 + (lane & 7));
    const uint32_t aCol = (uint32_t)((lane >> 4) * 16);
    const uint32_t bRow = (uint32_t)(lane & 7);
    const uint32_t bCol = (uint32_t)((((lane & 15) >> 3)) * 16);

    auto issueB = [&](int ch, uint32_t boff) {
        int ci0 = ch * 32;
        const __nv_bfloat16 *srch, *srcl; int Cs, off;
        if (ci0 < C1) { srch = in1h; srcl = in1l; Cs = C1;        off = ci0; }
        else          { srch = in2h; srcl = in2l; Cs = CINP - C1; off = ci0 - C1; }
        // 132 rows x 4 vec16 x 2 halves = 1056
        for (int e = tid; e < 1056; e += 256) {
            int half = (e >= 528); int ee = half ? e - 528 : e;
            int row = ee >> 2, v = ee & 3;
            int t = t0 - 2 + row;
            bool ok = (t >= 0) & (t < T_LEN);
            int tc = ok ? t : 0;
            uint32_t d = sb + boff + (uint32_t)half * 10560u + (uint32_t)row * 80u + (uint32_t)v * 16u;
            const __nv_bfloat16* s = (half ? srcl : srch) + ((size_t)b * T_LEN + tc) * Cs + off + v * 8;
            cpa16(d, s, ok);
        }
    };
    auto issueA = [&](int it, uint32_t aoff) {
        int ch = it / 5, k = it % 5, ci0 = ch * 32;
        // 128 rows x 4 vec16 x 2 halves = 1024
        for (int e = tid; e < 1024; e += 256) {
            int half = (e >= 512); int ee = e & 511;
            int row = ee >> 2, v = ee & 3;
            uint32_t d = sb + aoff + (uint32_t)half * 10240u + (uint32_t)row * 80u + (uint32_t)v * 16u;
            const __nv_bfloat16* s = (half ? wl : wh) + ((size_t)k * COUTP + mo * 128 + row) * CINP + ci0 + v * 8;
            cpa16(d, s, true);
        }
    };

    issueB(0, B_OFF0);
    issueA(0, A_OFF0);
    CP_COMMIT();

    for (int it = 0; it < ITER; it++) {
        int ch = it / 5, k = it % 5;
        uint32_t aoff = (it & 1) ? A_OFF1 : A_OFF0;
        uint32_t boff = (ch & 1) ? B_OFF1 : B_OFF0;
        if (it + 1 < ITER) {
            int ch1 = (it + 1) / 5;
            if (ch1 != ch) issueB(ch1, (ch1 & 1) ? B_OFF1 : B_OFF0);
            issueA(it + 1, ((it + 1) & 1) ? A_OFF1 : A_OFF0);
            CP_COMMIT();
            asm volatile("cp.async.wait_group 1;" ::: "memory");
        } else {
            asm volatile("cp.async.wait_group 0;" ::: "memory");
        }
        __syncthreads();

        uint32_t aH = sb + aoff + (uint32_t)(mw * 64) * 80u;
        uint32_t aL = aH + 10240u;
        uint32_t bH = sb + boff + (uint32_t)(nw * 32 + k) * 80u;
        uint32_t bL = bH + 10560u;
        #pragma unroll
        for (int ks = 0; ks < 2; ks++) {
            uint32_t ah[4][4], al[4][4], bh[4][2], bl[4][2];
            uint32_t kOff = (uint32_t)ks * 32u;
            #pragma unroll
            for (int mt = 0; mt < 4; mt++) ldsm4(ah[mt], aH + (uint32_t)(mt * 16) * 80u + aRow * 80u + kOff + aCol);
            #pragma unroll
            for (int nt = 0; nt < 4; nt++) ldsm2(bh[nt], bH + (uint32_t)(nt * 8) * 80u + bRow * 80u + kOff + bCol);
            #pragma unroll
            for (int mt = 0; mt < 4; mt++)
                #pragma unroll
                for (int nt = 0; nt < 4; nt++) mma16816(acc[mt][nt], ah[mt], bh[nt]);
            #pragma unroll
            for (int nt = 0; nt < 4; nt++) ldsm2(bl[nt], bL + (uint32_t)(nt * 8) * 80u + bRow * 80u + kOff + bCol);
            #pragma unroll
            for (int mt = 0; mt < 4; mt++)
                #pragma unroll
                for (int nt = 0; nt < 4; nt++) mma16816(acc[mt][nt], ah[mt], bl[nt]);
            #pragma unroll
            for (int mt = 0; mt < 4; mt++) ldsm4(al[mt], aL + (uint32_t)(mt * 16) * 80u + aRow * 80u + kOff + aCol);
            #pragma unroll
            for (int mt = 0; mt < 4; mt++)
                #pragma unroll
                for (int nt = 0; nt < 4; nt++) mma16816(acc[mt][nt], al[mt], bh[nt]);
        }
        __syncthreads();
    }

    // epilogue: bias + store raw [b][co][t]
    {
        int r = lane >> 2, c = (lane & 3) * 2;
        #pragma unroll
        for (int mt = 0; mt < 4; mt++) {
            int co0 = mo * 128 + mw * 64 + mt * 16 + r;
            int co1 = co0 + 8;
            float bv0 = (co0 < COUT) ? bias[co0] : 0.f;
            float bv1 = (co1 < COUT) ? bias[co1] : 0.f;
            #pragma unroll
            for (int nt = 0; nt < 4; nt++) {
                int t = t0 + nw * 32 + nt * 8 + c;
                float2 v0; v0.x = acc[mt][nt][0] + bv0; v0.y = acc[mt][nt][1] + bv0;
                float2 v1; v1.x = acc[mt][nt][2] + bv1; v1.y = acc[mt][nt][3] + bv1;
                *(float2*)(raw + ((size_t)b * COUTP + co0) * T_LEN + t) = v0;
                *(float2*)(raw + ((size_t)b * COUTP + co1) * T_LEN + t) = v1;
            }
        }
    }
}

// ---------------- LN + act + transpose + bf16 split ----------------
template<int CRAW,int GLU,int EXF>
__global__ void __launch_bounds__(256) ln_k(const float* __restrict__ raw,
    const float* __restrict__ ga, const float* __restrict__ be,
    __nv_bfloat16* __restrict__ oh, __nv_bfloat16* __restrict__ ol, float* __restrict__ of)
{
    constexpr int COUT = GLU ? CRAW/2 : CRAW;
    __shared__ float sS[8][33], sQ[8][33], sM[32], sR[32];
    __shared__ __nv_bfloat16 sTh[32*66], sTl[32*66];
    int b = blockIdx.y, t0 = blockIdx.x*32;
    int wg = threadIdx.x>>5, tt = threadIdx.x&31;
    const float* rb = raw + (size_t)b*CRAW*T_LEN + t0 + tt;
    float s=0.f, q=0.f;
    for (int c=wg; c<CRAW; c+=8){ float v=rb[(size_t)c*T_LEN]; s+=v; q+=v*v; }
    sS[wg][tt]=s; sQ[wg][tt]=q; __syncthreads();
    if (threadIdx.x<32){
        float S=0.f,Q=0.f;
        for(int g2=0;g2<8;g2++){S+=sS[g2][threadIdx.x];Q+=sQ[g2][threadIdx.x];}
        float m=S*(1.f/CRAW); float v=Q*(1.f/CRAW)-m*m;
        sM[threadIdx.x]=m; sR[threadIdx.x]=rsqrtf(v+1e-5f);
    }
    __syncthreads();
    float m=sM[tt], r=sR[tt];
    for (int c0=0;c0<COUT;c0+=64){
        #pragma unroll
        for (int i=0;i<8;i++){
            int c=c0+wg+8*i;
            float a=(rb[(size_t)c*T_LEN]-m)*r*ga[c]+be[c];
            if (GLU){
                float gt=(rb[(size_t)(c+COUT)*T_LEN]-m)*r*ga[c+COUT]+be[c+COUT];
                a=a*(1.f/(1.f+expf(-gt)));
            } else a = a>0.f? a : 0.2f*a;
            if (EXF) of[((size_t)b*COUT+c)*T_LEN + t0+tt] = a;
            __nv_bfloat16 h=__float2bfloat16(a);
            sTh[tt*66 + wg+8*i]=h;
            sTl[tt*66 + wg+8*i]=__float2bfloat16(a-__bfloat162float(h));
        }
        __syncthreads();
        {
            int row=threadIdx.x>>3, v=threadIdx.x&7;
            const uint32_t* ph=(const uint32_t*)sTh + row*33 + v*4;
            const uint32_t* pl=(const uint32_t*)sTl + row*33 + v*4;
            size_t go=((size_t)b*T_LEN + t0+row)*COUT + c0 + v*8;
            *(uint4*)(oh+go)=make_uint4(ph[0],ph[1],ph[2],ph[3]);
            *(uint4*)(ol+go)=make_uint4(pl[0],pl[1],pl[2],pl[3]);
        }
        __syncthreads();
    }
}

// ---------------- small helpers ----------------
__global__ void spknorm_k(const float* __restrict__ spk, float* __restrict__ o) {
    __shared__ float red[128];
    int r = blockIdx.x, t = threadIdx.x;
    float v = spk[r*128 + t];
    red[t] = v*v; __syncthreads();
    for (int s = 64; s > 0; s >>= 1) { if (t < s) red[t] += red[t+s]; __syncthreads(); }
    o[r*128 + t] = v * rsqrtf(red[0]);
}
__global__ void cbnorm_k(const float* __restrict__ cb, float* __restrict__ n) {
    int c = blockIdx.x*128 + threadIdx.x;
    if (c < 512) { float s=0.f; for (int d=0; d<64; d++){ float v=cb[c*64+d]; s+=v*v; } n[c]=s; }
}
__global__ void xprep_k(const float* __restrict__ x, __nv_bfloat16* __restrict__ oh, __nv_bfloat16* __restrict__ ol) {
    size_t e = (size_t)blockIdx.x*256 + threadIdx.x;
    int c = (int)(e & 127); size_t bt = e >> 7;
    float v = (c < 80) ? x[bt*80 + c] : 0.f;
    __nv_bfloat16 h = __float2bfloat16(v);
    oh[e] = h; ol[e] = __float2bfloat16(v - __bfloat162float(h));
}
__global__ void yeb_k(const int* __restrict__ y, const float* __restrict__ spk,
                      __nv_bfloat16* __restrict__ oh, __nv_bfloat16* __restrict__ ol) {
    int b = blockIdx.y, t = blockIdx.x*8 + (threadIdx.x>>5), lid = threadIdx.x & 31;
    int yi = y[(size_t)b*T_LEN + t];
    size_t base = ((size_t)b*T_LEN + t) * 128;
    for (int c = lid; c < 128; c += 32) {
        float v = spk[yi*128 + c];
        __nv_bfloat16 h = __float2bfloat16(v);
        oh[base+c] = h; ol[base+c] = __float2bfloat16(v - __bfloat162float(h));
    }
}
__global__ void zvqb_k(const int* __restrict__ idx, const float* __restrict__ cb,
                       __nv_bfloat16* __restrict__ oh, __nv_bfloat16* __restrict__ ol) {
    int b = blockIdx.y, t = blockIdx.x*8 + (threadIdx.x>>5), lid = threadIdx.x & 31;
    int ii = idx[(size_t)b*T_LEN + t];
    size_t base = ((size_t)b*T_LEN + t) * 64;
    for (int c = lid; c < 64; c += 32) {
        float v = cb[ii*64 + c];
        __nv_bfloat16 h = __float2bfloat16(v);
        oh[base+c] = h; ol[base+c] = __float2bfloat16(v - __bfloat162float(h));
    }
}
__global__ void out_k(const float* __restrict__ raw, float* __restrict__ out) {
    int b = blockIdx.y, tt = threadIdx.x & 31, g = threadIdx.x >> 5;
    int t = blockIdx.x*32 + tt;
    for (int f = g; f < 80; f += 8)
        out[((size_t)b*T_LEN + t)*80 + f] = raw[((size_t)b*128 + f)*T_LEN + t];
}
__global__ void wprep_k(const float* __restrict__ w, __nv_bfloat16* __restrict__ wh, __nv_bfloat16* __restrict__ wl,
                        int CIN, int COUT, int CINP, int COUTP, int K, int dec) {
    long e = (long)blockIdx.x*256 + threadIdx.x;
    if (e >= (long)K*COUTP*CINP) return;
    int ci = (int)(e % CINP); long r0 = e / CINP; int co = (int)(r0 % COUTP); int k = (int)(r0 / COUTP);
    float v = 0.f;
    if (ci < CIN && co < COUT)
        v = dec ? w[((size_t)ci*COUT + co)*K + (K-1-k)] : w[((size_t)co*CIN + ci)*K + k];
    __nv_bfloat16 h = __float2bfloat16(v);
    wh[e] = h; wl[e] = __float2bfloat16(v - __bfloat162float(h));
}
__global__ void wtrans_k(const float* __restrict__ w, float* __restrict__ wt, int CIN, int COUT) {
    int e = blockIdx.x*256 + threadIdx.x;
    if (e >= CIN*COUT) return;
    int co = e % COUT, ci = e / COUT;
    wt[e] = w[(size_t)co*CIN + ci];
}

// ---------------- fp32 1x1 conv (mlp / VQ argmin) ----------------
template<int CIN,int COUT,int G_CO,int TPT,int EPI>
__global__ __launch_bounds__(256,2) void mm_k(
    const float* __restrict__ in, const float* __restrict__ wt,
    const float* __restrict__ bias, float* __restrict__ out, int* __restrict__ oidx)
{
    constexpr int CIB=16, G_T=256/G_CO, TT=G_T*TPT, CPT=COUT/G_CO;
    constexpr int WE=CIB*COUT, IE=CIB*TT, NCB=CIN/CIB, RS=G_CO+1;
    extern __shared__ float smf[];
    float* sW=smf; float* sI=sW+WE; float* sRa=sI+IE; int* sRi=(int*)(sRa+TT*RS);
    const int tid=threadIdx.x, cg=tid%G_CO, tg=tid/G_CO;
    const int b=blockIdx.y, t0=blockIdx.x*TT;
    float acc[CPT][TPT];
    #pragma unroll
    for (int i=0;i<CPT;i++)
        #pragma unroll
        for (int t=0;t<TPT;t++) acc[i][t]=0.f;
    for (int cb=0; cb<NCB; cb++) {
        __syncthreads();
        const float* ws = wt + (size_t)cb*WE;
        for (int e=tid; e<WE; e+=256) sW[e]=ws[e];
        for (int e=tid; e<IE; e+=256) {
            int ci=e/TT, j=e%TT;
            sI[e] = in[((size_t)b*CIN + cb*CIB + ci)*T_LEN + t0 + j];
        }
        __syncthreads();
        #pragma unroll 1
        for (int ci=0; ci<CIB; ci++) {
            float rin[TPT];
            #pragma unroll
            for (int j=0;j<TPT;j++) rin[j]=sI[ci*TT + tg*TPT + j];
            #pragma unroll
            for (int i=0;i<CPT;i++) {
                float wv = sW[ci*COUT + cg + G_CO*i];
                #pragma unroll
                for (int t=0;t<TPT;t++) acc[i][t]=fmaf(wv, rin[t], acc[i][t]);
            }
        }
    }
    if constexpr (EPI == 1) {
        float bv[CPT];
        #pragma unroll
        for (int i=0;i<CPT;i++) bv[i]=bias[cg + G_CO*i];
        #pragma unroll
        for (int t=0;t<TPT;t++) {
            float best=3.4e38f; int bi=0;
            #pragma unroll
            for (int i=0;i<CPT;i++) {
                float v=bv[i]-2.f*acc[i][t]; int ii=cg+G_CO*i;
                if (v<best || (v==best && ii<bi)) { best=v; bi=ii; }
            }
            int tl=tg*TPT+t;
            sRa[tl*RS+cg]=best; sRi[tl*RS+cg]=bi;
        }
        __syncthreads();
        if (tid < TT) {
            float best=3.4e38f; int bi=0;
            for (int g=0; g<G_CO; g++) {
                float v=sRa[tid*RS+g]; int ii=sRi[tid*RS+g];
                if (v<best || (v==best && ii<bi)) { best=v; bi=ii; }
            }
            oidx[(size_t)b*T_LEN + t0 + tid] = bi;
        }
    } else {
        #pragma unroll
        for (int i=0;i<CPT;i++) {
            int co=cg+G_CO*i;
            float bv=bias[co];
            #pragma unroll
            for (int t=0;t<TPT;t++)
                out[((size_t)b*COUT+co)*T_LEN + t0 + tg*TPT + t] = acc[i][t]+bv;
        }
    }
}

// ---------------- launch ----------------
static const int GSM = 83200;
#define GEMM5(CINP_, i1h,i1l,C1_, i2h,i2l, biasp, COUT_, COUTP_) do { \
    auto kf = &gemm5_k<CINP_>; \
    cudaFuncSetAttribute(kf, cudaFuncAttributeMaxDynamicSharedMemorySize, GSM); \
    kf<<<dim3(32, B_SZ, (COUTP_)/128), 256, GSM>>>(i1h,i1l,C1_, i2h,i2l, wh,wl, biasp, COUT_, COUTP_, raw); \
} while (0)

extern "C" void kernel_launch(void* const* d_in, const int* in_sizes, int n_in,
                              void* d_out, int out_size) {
    (void)in_sizes; (void)n_in; (void)out_size;
    const float* x       = (const float*)d_in[0];
    const int*   y       = (const int*)  d_in[1];
    const float* enc_w1  = (const float*)d_in[2];
    const float* enc_b1  = (const float*)d_in[3];
    const float* enc_g1  = (const float*)d_in[4];
    const float* enc_bt1 = (const float*)d_in[5];
    const float* enc_w2  = (const float*)d_in[6];
    const float* enc_b2  = (const float*)d_in[7];
    const float* enc_g2  = (const float*)d_in[8];
    const float* enc_bt2 = (const float*)d_in[9];
    const float* enc_w3  = (const float*)d_in[10];
    const float* enc_b3  = (const float*)d_in[11];
    const float* enc_g3  = (const float*)d_in[12];
    const float* enc_bt3 = (const float*)d_in[13];
    const float* mlp_w   = (const float*)d_in[14];
    const float* mlp_b   = (const float*)d_in[15];
    const float* codebook= (const float*)d_in[16];
    const float* spk_emb = (const float*)d_in[17];
    const float* dec_w1  = (const float*)d_in[18];
    const float* dec_b1  = (const float*)d_in[19];
    const float* dec_g1  = (const float*)d_in[20];
    const float* dec_bt1 = (const float*)d_in[21];
    const float* dec_w2  = (const float*)d_in[22];
    const float* dec_b2  = (const float*)d_in[23];
    const float* dec_g2  = (const float*)d_in[24];
    const float* dec_bt2 = (const float*)d_in[25];
    const float* dec_w3  = (const float*)d_in[26];
    const float* dec_b3  = (const float*)d_in[27];
    float* outp = (float*)d_out;

    float *raw,*act32,*z,*wt,*cbt,*cbn,*spk; int* idx;
    __nv_bfloat16 *hAh,*hAl,*hBh,*hBl,*xh,*xl,*yeh,*yel,*zvh,*zvl,*wh,*wl;
    cudaGetSymbolAddress((void**)&raw,  g_raw);
    cudaGetSymbolAddress((void**)&act32,g_act32);
    cudaGetSymbolAddress((void**)&z,    g_z);
    cudaGetSymbolAddress((void**)&hAh,  g_hAh);  cudaGetSymbolAddress((void**)&hAl, g_hAl);
    cudaGetSymbolAddress((void**)&hBh,  g_hBh);  cudaGetSymbolAddress((void**)&hBl, g_hBl);
    cudaGetSymbolAddress((void**)&xh,   g_xh);   cudaGetSymbolAddress((void**)&xl,  g_xl);
    cudaGetSymbolAddress((void**)&yeh,  g_yeh);  cudaGetSymbolAddress((void**)&yel, g_yel);
    cudaGetSymbolAddress((void**)&zvh,  g_zvh);  cudaGetSymbolAddress((void**)&zvl, g_zvl);
    cudaGetSymbolAddress((void**)&wh,   g_wh);   cudaGetSymbolAddress((void**)&wl,  g_wl);
    cudaGetSymbolAddress((void**)&wt,   g_wt);
    cudaGetSymbolAddress((void**)&cbt,  g_cbt);
    cudaGetSymbolAddress((void**)&cbn,  g_cbn);
    cudaGetSymbolAddress((void**)&spk,  g_spk);
    cudaGetSymbolAddress((void**)&idx,  g_idx);

    // input prep
    xprep_k<<<(B_SZ*T_LEN*128)/256, 256>>>(x, xh, xl);
    spknorm_k<<<128, 128>>>(spk_emb, spk);
    yeb_k<<<dim3(T_LEN/8, B_SZ), 256>>>(y, spk, yeh, yel);

    // enc1: 80(pad128) -> 512
    wprep_k<<<(5*512*128+255)/256, 256>>>(enc_w1, wh, wl, 80, 512, 128, 512, 5, 0);
    GEMM5(128, xh, xl, 128, (const __nv_bfloat16*)nullptr, (const __nv_bfloat16*)nullptr, enc_b1, 512, 512);
    ln_k<512,0,0><<<dim3(128, B_SZ), 256>>>(raw, enc_g1, enc_bt1, hAh, hAl, nullptr);
    // enc2
    wprep_k<<<(5*512*512+255)/256, 256>>>(enc_w2, wh, wl, 512, 512, 512, 512, 5, 0);
    GEMM5(512, hAh, hAl, 512, (const __nv_bfloat16*)nullptr, (const __nv_bfloat16*)nullptr, enc_b2, 512, 512);
    ln_k<512,0,0><<<dim3(128, B_SZ), 256>>>(raw, enc_g2, enc_bt2, hBh, hBl, nullptr);
    // enc3 (also emit fp32 for mlp)
    wprep_k<<<(5*512*512+255)/256, 256>>>(enc_w3, wh, wl, 512, 512, 512, 512, 5, 0);
    GEMM5(512, hBh, hBl, 512, (const __nv_bfloat16*)nullptr, (const __nv_bfloat16*)nullptr, enc_b3, 512, 512);
    ln_k<512,0,1><<<dim3(128, B_SZ), 256>>>(raw, enc_g3, enc_bt3, hAh, hAl, act32);

    // mlp 1x1: 512 -> 64 (fp32 exact path into VQ)
    wtrans_k<<<(512*64+255)/256, 256>>>(mlp_w, wt, 512, 64);
    mm_k<512,64,32,8,0><<<dim3(T_LEN/64, B_SZ), 256, (16*64+16*64+64*33*2)*4>>>(act32, wt, mlp_b, z, nullptr);
    // VQ argmin (exact fp32)
    wtrans_k<<<(64*512+255)/256, 256>>>(codebook, cbt, 64, 512);
    cbnorm_k<<<4, 128>>>(codebook, cbn);
    {
        constexpr int SB = (16*512 + 16*32 + 32*65*2)*4;
        auto kf = &mm_k<64,512,64,8,1>;
        cudaFuncSetAttribute(kf, cudaFuncAttributeMaxDynamicSharedMemorySize, SB);
        kf<<<dim3(T_LEN/32, B_SZ), 256, SB>>>(z, cbt, cbn, nullptr, idx);
    }
    zvqb_k<<<dim3(T_LEN/8, B_SZ), 256>>>(idx, codebook, zvh, zvl);

    // dec1: (64+128) -> 1024, LN+GLU -> 512
    wprep_k<<<(5*1024*192+255)/256, 256>>>(dec_w1, wh, wl, 192, 1024, 192, 1024, 5, 1);
    GEMM5(192, zvh, zvl, 64, yeh, yel, dec_b1, 1024, 1024);
    ln_k<1024,1,0><<<dim3(128, B_SZ), 256>>>(raw, dec_g1, dec_bt1, hAh, hAl, nullptr);
    // dec2: (512+128) -> 1024, LN+GLU -> 512
    wprep_k<<<(5*1024*640+255)/256, 256>>>(dec_w2, wh, wl, 640, 1024, 640, 1024, 5, 1);
    GEMM5(640, hAh, hAl, 512, yeh, yel, dec_b2, 1024, 1024);
    ln_k<1024,1,0><<<dim3(128, B_SZ), 256>>>(raw, dec_g2, dec_bt2, hBh, hBl, nullptr);
    // dec3: (512+128) -> 80 (pad 128)
    wprep_k<<<(5*128*640+255)/256, 256>>>(dec_w3, wh, wl, 640, 80, 640, 128, 5, 1);
    GEMM5(640, hBh, hBl, 512, yeh, yel, dec_b3, 80, 128);
    out_k<<<dim3(T_LEN/32, B_SZ), 256>>>(raw, outp);
}

// round 10
// speedup vs baseline: 7.3377x; 1.2188x over previous
#include <cuda_runtime.h>
#include <cuda_fp16.h>
#include <cuda_bf16.h>
#include <math.h>
#include <stdint.h>

#define T_LEN 4096
#define B_SZ  16

// ---------------- scratch (all GEMM operands are raw 16-bit; type known by prep/mma) ----------------
__device__ float    g_raw  [16ll*1024*4096];
__device__ float    g_act32[16ll*512*4096];
__device__ float    g_z    [16ll*64*4096];
__device__ uint16_t g_hAh[16ll*4096*512], g_hAl[16ll*4096*512];
__device__ uint16_t g_hBh[16ll*4096*512], g_hBl[16ll*4096*512];
__device__ uint16_t g_xh [16ll*4096*128], g_xl [16ll*4096*128];
__device__ uint16_t g_yeh[16ll*4096*128], g_yel[16ll*4096*128];
__device__ uint16_t g_zvh[16ll*4096*64],  g_zvl[16ll*4096*64];
__device__ uint16_t g_wh [5ll*1024*640],  g_wl [5ll*1024*640];
__device__ float    g_wt [512*64];
__device__ float    g_cbt[64*512];
__device__ float    g_cbn[512];
__device__ float    g_spk[128*128];
__device__ int      g_idx[16*4096];

// ---------------- conversion helpers ----------------
__device__ __forceinline__ uint16_t f2bf(float v) {
    __nv_bfloat16 h = __float2bfloat16(v); return *(uint16_t*)&h;
}
__device__ __forceinline__ float bf2f(uint16_t u) {
    __nv_bfloat16 h = *(__nv_bfloat16*)&u; return __bfloat162float(h);
}
__device__ __forceinline__ uint16_t f2hf(float v) {
    __half h = __float2half(v); return *(uint16_t*)&h;
}
__device__ __forceinline__ float hf2f(uint16_t u) {
    __half h = *(__half*)&u; return __half2float(h);
}

// ---------------- PTX helpers ----------------
__device__ __forceinline__ uint32_t s32(const void* p) {
    uint32_t a;
    asm("{ .reg .u64 t; cvta.to.shared.u64 t, %1; cvt.u32.u64 %0, t; }" : "=r"(a) : "l"(p));
    return a;
}
__device__ __forceinline__ void cpa16(uint32_t d, const void* s, bool v) {
    int sz = v ? 16 : 0;
    asm volatile("cp.async.cg.shared.global [%0], [%1], 16, %2;" :: "r"(d), "l"(s), "r"(sz) : "memory");
}
#define CP_COMMIT() asm volatile("cp.async.commit_group;" ::: "memory")
__device__ __forceinline__ void ldsm4(uint32_t* r, uint32_t a) {
    asm volatile("ldmatrix.sync.aligned.m8n8.x4.shared.b16 {%0,%1,%2,%3}, [%4];"
                 : "=r"(r[0]),"=r"(r[1]),"=r"(r[2]),"=r"(r[3]) : "r"(a));
}
__device__ __forceinline__ void ldsm2(uint32_t* r, uint32_t a) {
    asm volatile("ldmatrix.sync.aligned.m8n8.x2.shared.b16 {%0,%1}, [%2];"
                 : "=r"(r[0]),"=r"(r[1]) : "r"(a));
}
__device__ __forceinline__ void mma_bf16(float* d, const uint32_t* a, const uint32_t* b) {
    asm volatile("mma.sync.aligned.m16n8k16.row.col.f32.bf16.bf16.f32 "
                 "{%0,%1,%2,%3}, {%4,%5,%6,%7}, {%8,%9}, {%0,%1,%2,%3};"
                 : "+f"(d[0]), "+f"(d[1]), "+f"(d[2]), "+f"(d[3])
                 : "r"(a[0]), "r"(a[1]), "r"(a[2]), "r"(a[3]), "r"(b[0]), "r"(b[1]));
}
__device__ __forceinline__ void mma_f16(float* d, const uint32_t* a, const uint32_t* b) {
    asm volatile("mma.sync.aligned.m16n8k16.row.col.f32.f16.f16.f32 "
                 "{%0,%1,%2,%3}, {%4,%5,%6,%7}, {%8,%9}, {%0,%1,%2,%3};"
                 : "+f"(d[0]), "+f"(d[1]), "+f"(d[2]), "+f"(d[3])
                 : "r"(a[0]), "r"(a[1]), "r"(a[2]), "r"(a[3]), "r"(b[0]), "r"(b[1]));
}

// ---------------- mma.sync K=5 implicit conv GEMM ----------------
// MODE 0: bf16, A hi/lo split, 3 products (encoder — flip-free precision 2^-16)
// MODE 1: fp16, A single,   2 products (decoder — ~2^-12/layer)
// grid (T/128, B, COUTP/128), block 256 (8 warps, warp tile 64co x 32t).
template<int CINP, int MODE>
__global__ void __launch_bounds__(256,2) gemm5_k(
    const uint16_t* __restrict__ in1h, const uint16_t* __restrict__ in1l, int C1,
    const uint16_t* __restrict__ in2h, const uint16_t* __restrict__ in2l,
    const uint16_t* __restrict__ wh,   const uint16_t* __restrict__ wl,
    const float* __restrict__ bias, int COUT, int COUTP,
    float* __restrict__ raw)
{
    constexpr int NCH  = CINP / 32;
    constexpr int ITER = NCH * 5;
    constexpr uint32_t A_BUF = (MODE == 0) ? 20480u : 10240u;
    extern __shared__ char smc[];
    const uint32_t sb = s32(smc);
    const uint32_t B_OFF0 = 0u, B_OFF1 = 21120u;
    const uint32_t A_OFF0 = 42240u, A_OFF1 = 42240u + A_BUF;

    const int tid = threadIdx.x, lane = tid & 31, wid = tid >> 5;
    const int mw = wid & 1, nw = wid >> 1;
    const int t0 = blockIdx.x * 128, b = blockIdx.y, mo = blockIdx.z;

    float acc[4][4][4];
    #pragma unroll
    for (int i = 0; i < 4; i++)
        #pragma unroll
        for (int j = 0; j < 4; j++)
            #pragma unroll
            for (int q = 0; q < 4; q++) acc[i][j][q] = 0.f;

    const uint32_t aRow = (uint32_t)(((lane >> 3) & 1) * 8 + (lane & 7));
    const uint32_t aCol = (uint32_t)((lane >> 4) * 16);
    const uint32_t bRow = (uint32_t)(lane & 7);
    const uint32_t bCol = (uint32_t)((((lane & 15) >> 3)) * 16);

    auto issueB = [&](int ch, uint32_t boff) {
        int ci0 = ch * 32;
        const uint16_t *srch, *srcl; int Cs, off;
        if (ci0 < C1) { srch = in1h; srcl = in1l; Cs = C1;        off = ci0; }
        else          { srch = in2h; srcl = in2l; Cs = CINP - C1; off = ci0 - C1; }
        for (int e = tid; e < 1056; e += 256) {       // 132 rows x 4 vec16 x 2 halves
            int half_ = (e >= 528); int ee = half_ ? e - 528 : e;
            int row = ee >> 2, v = ee & 3;
            int t = t0 - 2 + row;
            bool ok = (t >= 0) & (t < T_LEN);
            int tc = ok ? t : 0;
            uint32_t d = sb + boff + (uint32_t)half_ * 10560u + (uint32_t)row * 80u + (uint32_t)v * 16u;
            const uint16_t* s = (half_ ? srcl : srch) + ((size_t)b * T_LEN + tc) * Cs + off + v * 8;
            cpa16(d, s, ok);
        }
    };
    auto issueA = [&](int it, uint32_t aoff) {
        int ch = it / 5, k = it % 5, ci0 = ch * 32;
        constexpr int AE = (MODE == 0) ? 1024 : 512;  // rows x vec16 x halves
        for (int e = tid; e < AE; e += 256) {
            int half_ = (e >= 512); int ee = e & 511;
            int row = ee >> 2, v = ee & 3;
            uint32_t d = sb + aoff + (uint32_t)half_ * 10240u + (uint32_t)row * 80u + (uint32_t)v * 16u;
            const uint16_t* s = (half_ ? wl : wh) + ((size_t)k * COUTP + mo * 128 + row) * CINP + ci0 + v * 8;
            cpa16(d, s, true);
        }
    };

    issueB(0, B_OFF0);
    issueA(0, A_OFF0);
    CP_COMMIT();

    for (int it = 0; it < ITER; it++) {
        int ch = it / 5, k = it % 5;
        uint32_t aoff = (it & 1) ? A_OFF1 : A_OFF0;
        uint32_t boff = (ch & 1) ? B_OFF1 : B_OFF0;
        if (it + 1 < ITER) {
            int ch1 = (it + 1) / 5;
            if (ch1 != ch) issueB(ch1, (ch1 & 1) ? B_OFF1 : B_OFF0);
            issueA(it + 1, ((it + 1) & 1) ? A_OFF1 : A_OFF0);
            CP_COMMIT();
            asm volatile("cp.async.wait_group 1;" ::: "memory");
        } else {
            asm volatile("cp.async.wait_group 0;" ::: "memory");
        }
        __syncthreads();

        uint32_t aH = sb + aoff + (uint32_t)(mw * 64) * 80u;
        uint32_t bH = sb + boff + (uint32_t)(nw * 32 + k) * 80u;
        uint32_t bL = bH + 10560u;
        #pragma unroll
        for (int ks = 0; ks < 2; ks++) {
            uint32_t ah[4][4], bh[4][2], bl[4][2];
            uint32_t kOff = (uint32_t)ks * 32u;
            #pragma unroll
            for (int mt = 0; mt < 4; mt++) ldsm4(ah[mt], aH + (uint32_t)(mt * 16) * 80u + aRow * 80u + kOff + aCol);
            #pragma unroll
            for (int nt = 0; nt < 4; nt++) ldsm2(bh[nt], bH + (uint32_t)(nt * 8) * 80u + bRow * 80u + kOff + bCol);
            #pragma unroll
            for (int mt = 0; mt < 4; mt++)
                #pragma unroll
                for (int nt = 0; nt < 4; nt++) {
                    if constexpr (MODE == 0) mma_bf16(acc[mt][nt], ah[mt], bh[nt]);
                    else                     mma_f16 (acc[mt][nt], ah[mt], bh[nt]);
                }
            #pragma unroll
            for (int nt = 0; nt < 4; nt++) ldsm2(bl[nt], bL + (uint32_t)(nt * 8) * 80u + bRow * 80u + kOff + bCol);
            #pragma unroll
            for (int mt = 0; mt < 4; mt++)
                #pragma unroll
                for (int nt = 0; nt < 4; nt++) {
                    if constexpr (MODE == 0) mma_bf16(acc[mt][nt], ah[mt], bl[nt]);
                    else                     mma_f16 (acc[mt][nt], ah[mt], bl[nt]);
                }
            if constexpr (MODE == 0) {      // third product: A-lo x B-hi
                uint32_t al[4][4];
                uint32_t aL = aH + 10240u;
                #pragma unroll
                for (int mt = 0; mt < 4; mt++) ldsm4(al[mt], aL + (uint32_t)(mt * 16) * 80u + aRow * 80u + kOff + aCol);
                #pragma unroll
                for (int mt = 0; mt < 4; mt++)
                    #pragma unroll
                    for (int nt = 0; nt < 4; nt++) mma_bf16(acc[mt][nt], al[mt], bh[nt]);
            }
        }
        __syncthreads();
    }

    // epilogue: bias + store raw [b][co][t]
    {
        int r = lane >> 2, c = (lane & 3) * 2;
        #pragma unroll
        for (int mt = 0; mt < 4; mt++) {
            int co0 = mo * 128 + mw * 64 + mt * 16 + r;
            int co1 = co0 + 8;
            float bv0 = (co0 < COUT) ? bias[co0] : 0.f;
            float bv1 = (co1 < COUT) ? bias[co1] : 0.f;
            #pragma unroll
            for (int nt = 0; nt < 4; nt++) {
                int t = t0 + nw * 32 + nt * 8 + c;
                float2 v0; v0.x = acc[mt][nt][0] + bv0; v0.y = acc[mt][nt][1] + bv0;
                float2 v1; v1.x = acc[mt][nt][2] + bv1; v1.y = acc[mt][nt][3] + bv1;
                *(float2*)(raw + ((size_t)b * COUTP + co0) * T_LEN + t) = v0;
                *(float2*)(raw + ((size_t)b * COUTP + co1) * T_LEN + t) = v1;
            }
        }
    }
}

// ---------------- LN + act + transpose + 16-bit split ----------------
// OUT: 0 = bf16 hi/lo pair, 1 = fp16 hi/lo pair, 2 = fp32 only (no pair output)
template<int CRAW,int GLU,int OUT,int EXF>
__global__ void __launch_bounds__(256) ln_k(const float* __restrict__ raw,
    const float* __restrict__ ga, const float* __restrict__ be,
    uint16_t* __restrict__ oh, uint16_t* __restrict__ ol, float* __restrict__ of)
{
    constexpr int COUT = GLU ? CRAW/2 : CRAW;
    __shared__ float sS[8][33], sQ[8][33], sM[32], sR[32];
    __shared__ uint16_t sTh[32*66], sTl[32*66];
    int b = blockIdx.y, t0 = blockIdx.x*32;
    int wg = threadIdx.x>>5, tt = threadIdx.x&31;
    const float* rb = raw + (size_t)b*CRAW*T_LEN + t0 + tt;
    float s=0.f, q=0.f;
    for (int c=wg; c<CRAW; c+=8){ float v=rb[(size_t)c*T_LEN]; s+=v; q+=v*v; }
    sS[wg][tt]=s; sQ[wg][tt]=q; __syncthreads();
    if (threadIdx.x<32){
        float S=0.f,Q=0.f;
        for(int g2=0;g2<8;g2++){S+=sS[g2][threadIdx.x];Q+=sQ[g2][threadIdx.x];}
        float m=S*(1.f/CRAW); float v=Q*(1.f/CRAW)-m*m;
        sM[threadIdx.x]=m; sR[threadIdx.x]=rsqrtf(v+1e-5f);
    }
    __syncthreads();
    float m=sM[tt], r=sR[tt];
    for (int c0=0;c0<COUT;c0+=64){
        #pragma unroll
        for (int i=0;i<8;i++){
            int c=c0+wg+8*i;
            float a=(rb[(size_t)c*T_LEN]-m)*r*ga[c]+be[c];
            if (GLU){
                float gt=(rb[(size_t)(c+COUT)*T_LEN]-m)*r*ga[c+COUT]+be[c+COUT];
                a=a*(1.f/(1.f+expf(-gt)));
            } else a = a>0.f? a : 0.2f*a;
            if (EXF) of[((size_t)b*COUT+c)*T_LEN + t0+tt] = a;
            if constexpr (OUT == 0) {
                uint16_t h = f2bf(a);
                sTh[tt*66 + wg+8*i] = h;
                sTl[tt*66 + wg+8*i] = f2bf(a - bf2f(h));
            } else if constexpr (OUT == 1) {
                uint16_t h = f2hf(a);
                sTh[tt*66 + wg+8*i] = h;
                sTl[tt*66 + wg+8*i] = f2hf(a - hf2f(h));
            }
        }
        if constexpr (OUT != 2) {
            __syncthreads();
            {
                int row=threadIdx.x>>3, v=threadIdx.x&7;
                const uint32_t* ph=(const uint32_t*)sTh + row*33 + v*4;
                const uint32_t* pl=(const uint32_t*)sTl + row*33 + v*4;
                size_t go=((size_t)b*T_LEN + t0+row)*COUT + c0 + v*8;
                *(uint4*)(oh+go)=make_uint4(ph[0],ph[1],ph[2],ph[3]);
                *(uint4*)(ol+go)=make_uint4(pl[0],pl[1],pl[2],pl[3]);
            }
            __syncthreads();
        }
    }
}

// ---------------- small helpers ----------------
__global__ void spknorm_k(const float* __restrict__ spk, float* __restrict__ o) {
    __shared__ float red[128];
    int r = blockIdx.x, t = threadIdx.x;
    float v = spk[r*128 + t];
    red[t] = v*v; __syncthreads();
    for (int s = 64; s > 0; s >>= 1) { if (t < s) red[t] += red[t+s]; __syncthreads(); }
    o[r*128 + t] = v * rsqrtf(red[0]);
}
__global__ void cbnorm_k(const float* __restrict__ cb, float* __restrict__ n) {
    int c = blockIdx.x*128 + threadIdx.x;
    if (c < 512) { float s=0.f; for (int d=0; d<64; d++){ float v=cb[c*64+d]; s+=v*v; } n[c]=s; }
}
__global__ void xprep_k(const float* __restrict__ x, uint16_t* __restrict__ oh, uint16_t* __restrict__ ol) {
    size_t e = (size_t)blockIdx.x*256 + threadIdx.x;
    int c = (int)(e & 127); size_t bt = e >> 7;
    float v = (c < 80) ? x[bt*80 + c] : 0.f;
    uint16_t h = f2bf(v);
    oh[e] = h; ol[e] = f2bf(v - bf2f(h));
}
__global__ void yeb_k(const int* __restrict__ y, const float* __restrict__ spk,
                      uint16_t* __restrict__ oh, uint16_t* __restrict__ ol) {
    int b = blockIdx.y, t = blockIdx.x*8 + (threadIdx.x>>5), lid = threadIdx.x & 31;
    int yi = y[(size_t)b*T_LEN + t];
    size_t base = ((size_t)b*T_LEN + t) * 128;
    for (int c = lid; c < 128; c += 32) {
        float v = spk[yi*128 + c];
        uint16_t h = f2hf(v);
        oh[base+c] = h; ol[base+c] = f2hf(v - hf2f(h));
    }
}
__global__ void zvqb_k(const int* __restrict__ idx, const float* __restrict__ cb,
                       uint16_t* __restrict__ oh, uint16_t* __restrict__ ol) {
    int b = blockIdx.y, t = blockIdx.x*8 + (threadIdx.x>>5), lid = threadIdx.x & 31;
    int ii = idx[(size_t)b*T_LEN + t];
    size_t base = ((size_t)b*T_LEN + t) * 64;
    for (int c = lid; c < 64; c += 32) {
        float v = cb[ii*64 + c];
        uint16_t h = f2hf(v);
        oh[base+c] = h; ol[base+c] = f2hf(v - hf2f(h));
    }
}
__global__ void out_k(const float* __restrict__ raw, float* __restrict__ out) {
    int b = blockIdx.y, tt = threadIdx.x & 31, g = threadIdx.x >> 5;
    int t = blockIdx.x*32 + tt;
    for (int f = g; f < 80; f += 8)
        out[((size_t)b*T_LEN + t)*80 + f] = raw[((size_t)b*128 + f)*T_LEN + t];
}
// mode 0: bf16 hi/lo (encoder); mode 1: fp16 single (decoder, dec handles ConvT flip)
__global__ void wprep_k(const float* __restrict__ w, uint16_t* __restrict__ wh, uint16_t* __restrict__ wl,
                        int CIN, int COUT, int CINP, int COUTP, int K, int dec, int mode) {
    long e = (long)blockIdx.x*256 + threadIdx.x;
    if (e >= (long)K*COUTP*CINP) return;
    int ci = (int)(e % CINP); long r0 = e / CINP; int co = (int)(r0 % COUTP); int k = (int)(r0 / COUTP);
    float v = 0.f;
    if (ci < CIN && co < COUT)
        v = dec ? w[((size_t)ci*COUT + co)*K + (K-1-k)] : w[((size_t)co*CIN + ci)*K + k];
    if (mode == 0) {
        uint16_t h = f2bf(v);
        wh[e] = h; wl[e] = f2bf(v - bf2f(h));
    } else {
        wh[e] = f2hf(v);
    }
}
__global__ void wtrans_k(const float* __restrict__ w, float* __restrict__ wt, int CIN, int COUT) {
    int e = blockIdx.x*256 + threadIdx.x;
    if (e >= CIN*COUT) return;
    int co = e % COUT, ci = e / COUT;
    wt[e] = w[(size_t)co*CIN + ci];
}

// ---------------- fp32 1x1 conv (mlp / VQ argmin) ----------------
template<int CIN,int COUT,int G_CO,int TPT,int EPI>
__global__ __launch_bounds__(256,2) void mm_k(
    const float* __restrict__ in, const float* __restrict__ wt,
    const float* __restrict__ bias, float* __restrict__ out, int* __restrict__ oidx)
{
    constexpr int CIB=16, G_T=256/G_CO, TT=G_T*TPT, CPT=COUT/G_CO;
    constexpr int WE=CIB*COUT, IE=CIB*TT, NCB=CIN/CIB, RS=G_CO+1;
    extern __shared__ float smf[];
    float* sW=smf; float* sI=sW+WE; float* sRa=sI+IE; int* sRi=(int*)(sRa+TT*RS);
    const int tid=threadIdx.x, cg=tid%G_CO, tg=tid/G_CO;
    const int b=blockIdx.y, t0=blockIdx.x*TT;
    float acc[CPT][TPT];
    #pragma unroll
    for (int i=0;i<CPT;i++)
        #pragma unroll
        for (int t=0;t<TPT;t++) acc[i][t]=0.f;
    for (int cb=0; cb<NCB; cb++) {
        __syncthreads();
        const float* ws = wt + (size_t)cb*WE;
        for (int e=tid; e<WE; e+=256) sW[e]=ws[e];
        for (int e=tid; e<IE; e+=256) {
            int ci=e/TT, j=e%TT;
            sI[e] = in[((size_t)b*CIN + cb*CIB + ci)*T_LEN + t0 + j];
        }
        __syncthreads();
        #pragma unroll 1
        for (int ci=0; ci<CIB; ci++) {
            float rin[TPT];
            #pragma unroll
            for (int j=0;j<TPT;j++) rin[j]=sI[ci*TT + tg*TPT + j];
            #pragma unroll
            for (int i=0;i<CPT;i++) {
                float wv = sW[ci*COUT + cg + G_CO*i];
                #pragma unroll
                for (int t=0;t<TPT;t++) acc[i][t]=fmaf(wv, rin[t], acc[i][t]);
            }
        }
    }
    if constexpr (EPI == 1) {
        float bv[CPT];
        #pragma unroll
        for (int i=0;i<CPT;i++) bv[i]=bias[cg + G_CO*i];
        #pragma unroll
        for (int t=0;t<TPT;t++) {
            float best=3.4e38f; int bi=0;
            #pragma unroll
            for (int i=0;i<CPT;i++) {
                float v=bv[i]-2.f*acc[i][t]; int ii=cg+G_CO*i;
                if (v<best || (v==best && ii<bi)) { best=v; bi=ii; }
            }
            int tl=tg*TPT+t;
            sRa[tl*RS+cg]=best; sRi[tl*RS+cg]=bi;
        }
        __syncthreads();
        if (tid < TT) {
            float best=3.4e38f; int bi=0;
            for (int g=0; g<G_CO; g++) {
                float v=sRa[tid*RS+g]; int ii=sRi[tid*RS+g];
                if (v<best || (v==best && ii<bi)) { best=v; bi=ii; }
            }
            oidx[(size_t)b*T_LEN + t0 + tid] = bi;
        }
    } else {
        #pragma unroll
        for (int i=0;i<CPT;i++) {
            int co=cg+G_CO*i;
            float bv=bias[co];
            #pragma unroll
            for (int t=0;t<TPT;t++)
                out[((size_t)b*COUT+co)*T_LEN + t0 + tg*TPT + t] = acc[i][t]+bv;
        }
    }
}

// ---------------- launch ----------------
#define GEMM5(CINP_, MODE_, i1h,i1l,C1_, i2h,i2l, biasp, COUT_, COUTP_) do { \
    constexpr int SMB_ = 42240 + 2 * ((MODE_) == 0 ? 20480 : 10240); \
    auto kf = &gemm5_k<CINP_, MODE_>; \
    cudaFuncSetAttribute(kf, cudaFuncAttributeMaxDynamicSharedMemorySize, SMB_); \
    kf<<<dim3(32, B_SZ, (COUTP_)/128), 256, SMB_>>>(i1h,i1l,C1_, i2h,i2l, wh,wl, biasp, COUT_, COUTP_, raw); \
} while (0)

extern "C" void kernel_launch(void* const* d_in, const int* in_sizes, int n_in,
                              void* d_out, int out_size) {
    (void)in_sizes; (void)n_in; (void)out_size;
    const float* x       = (const float*)d_in[0];
    const int*   y       = (const int*)  d_in[1];
    const float* enc_w1  = (const float*)d_in[2];
    const float* enc_b1  = (const float*)d_in[3];
    const float* enc_g1  = (const float*)d_in[4];
    const float* enc_bt1 = (const float*)d_in[5];
    const float* enc_w2  = (const float*)d_in[6];
    const float* enc_b2  = (const float*)d_in[7];
    const float* enc_g2  = (const float*)d_in[8];
    const float* enc_bt2 = (const float*)d_in[9];
    const float* enc_w3  = (const float*)d_in[10];
    const float* enc_b3  = (const float*)d_in[11];
    const float* enc_g3  = (const float*)d_in[12];
    const float* enc_bt3 = (const float*)d_in[13];
    const float* mlp_w   = (const float*)d_in[14];
    const float* mlp_b   = (const float*)d_in[15];
    const float* codebook= (const float*)d_in[16];
    const float* spk_emb = (const float*)d_in[17];
    const float* dec_w1  = (const float*)d_in[18];
    const float* dec_b1  = (const float*)d_in[19];
    const float* dec_g1  = (const float*)d_in[20];
    const float* dec_bt1 = (const float*)d_in[21];
    const float* dec_w2  = (const float*)d_in[22];
    const float* dec_b2  = (const float*)d_in[23];
    const float* dec_g2  = (const float*)d_in[24];
    const float* dec_bt2 = (const float*)d_in[25];
    const float* dec_w3  = (const float*)d_in[26];
    const float* dec_b3  = (const float*)d_in[27];
    float* outp = (float*)d_out;

    float *raw,*act32,*z,*wt,*cbt,*cbn,*spk; int* idx;
    uint16_t *hAh,*hAl,*hBh,*hBl,*xh,*xl,*yeh,*yel,*zvh,*zvl,*wh,*wl;
    cudaGetSymbolAddress((void**)&raw,  g_raw);
    cudaGetSymbolAddress((void**)&act32,g_act32);
    cudaGetSymbolAddress((void**)&z,    g_z);
    cudaGetSymbolAddress((void**)&hAh,  g_hAh);  cudaGetSymbolAddress((void**)&hAl, g_hAl);
    cudaGetSymbolAddress((void**)&hBh,  g_hBh);  cudaGetSymbolAddress((void**)&hBl, g_hBl);
    cudaGetSymbolAddress((void**)&xh,   g_xh);   cudaGetSymbolAddress((void**)&xl,  g_xl);
    cudaGetSymbolAddress((void**)&yeh,  g_yeh);  cudaGetSymbolAddress((void**)&yel, g_yel);
    cudaGetSymbolAddress((void**)&zvh,  g_zvh);  cudaGetSymbolAddress((void**)&zvl, g_zvl);
    cudaGetSymbolAddress((void**)&wh,   g_wh);   cudaGetSymbolAddress((void**)&wl,  g_wl);
    cudaGetSymbolAddress((void**)&wt,   g_wt);
    cudaGetSymbolAddress((void**)&cbt,  g_cbt);
    cudaGetSymbolAddress((void**)&cbn,  g_cbn);
    cudaGetSymbolAddress((void**)&spk,  g_spk);
    cudaGetSymbolAddress((void**)&idx,  g_idx);

    // input prep
    xprep_k<<<(B_SZ*T_LEN*128)/256, 256>>>(x, xh, xl);
    spknorm_k<<<128, 128>>>(spk_emb, spk);
    yeb_k<<<dim3(T_LEN/8, B_SZ), 256>>>(y, spk, yeh, yel);

    // ===== encoder: bf16 3-product (MODE 0) =====
    wprep_k<<<(5*512*128+255)/256, 256>>>(enc_w1, wh, wl, 80, 512, 128, 512, 5, 0, 0);
    GEMM5(128, 0, xh, xl, 128, (const uint16_t*)nullptr, (const uint16_t*)nullptr, enc_b1, 512, 512);
    ln_k<512,0,0,0><<<dim3(128, B_SZ), 256>>>(raw, enc_g1, enc_bt1, hAh, hAl, nullptr);
    wprep_k<<<(5*512*512+255)/256, 256>>>(enc_w2, wh, wl, 512, 512, 512, 512, 5, 0, 0);
    GEMM5(512, 0, hAh, hAl, 512, (const uint16_t*)nullptr, (const uint16_t*)nullptr, enc_b2, 512, 512);
    ln_k<512,0,0,0><<<dim3(128, B_SZ), 256>>>(raw, enc_g2, enc_bt2, hBh, hBl, nullptr);
    wprep_k<<<(5*512*512+255)/256, 256>>>(enc_w3, wh, wl, 512, 512, 512, 512, 5, 0, 0);
    GEMM5(512, 0, hBh, hBl, 512, (const uint16_t*)nullptr, (const uint16_t*)nullptr, enc_b3, 512, 512);
    ln_k<512,0,2,1><<<dim3(128, B_SZ), 256>>>(raw, enc_g3, enc_bt3, nullptr, nullptr, act32);

    // ===== mlp + VQ (exact fp32) =====
    wtrans_k<<<(512*64+255)/256, 256>>>(mlp_w, wt, 512, 64);
    mm_k<512,64,32,8,0><<<dim3(T_LEN/64, B_SZ), 256, (16*64+16*64+64*33*2)*4>>>(act32, wt, mlp_b, z, nullptr);
    wtrans_k<<<(64*512+255)/256, 256>>>(codebook, cbt, 64, 512);
    cbnorm_k<<<4, 128>>>(codebook, cbn);
    {
        constexpr int SB = (16*512 + 16*32 + 32*65*2)*4;
        auto kf = &mm_k<64,512,64,8,1>;
        cudaFuncSetAttribute(kf, cudaFuncAttributeMaxDynamicSharedMemorySize, SB);
        kf<<<dim3(T_LEN/32, B_SZ), 256, SB>>>(z, cbt, cbn, nullptr, idx);
    }
    zvqb_k<<<dim3(T_LEN/8, B_SZ), 256>>>(idx, codebook, zvh, zvl);

    // ===== decoder: fp16 2-product (MODE 1) =====
    wprep_k<<<(5*1024*192+255)/256, 256>>>(dec_w1, wh, wl, 192, 1024, 192, 1024, 5, 1, 1);
    GEMM5(192, 1, zvh, zvl, 64, yeh, yel, dec_b1, 1024, 1024);
    ln_k<1024,1,1,0><<<dim3(128, B_SZ), 256>>>(raw, dec_g1, dec_bt1, hAh, hAl, nullptr);
    wprep_k<<<(5*1024*640+255)/256, 256>>>(dec_w2, wh, wl, 640, 1024, 640, 1024, 5, 1, 1);
    GEMM5(640, 1, hAh, hAl, 512, yeh, yel, dec_b2, 1024, 1024);
    ln_k<1024,1,1,0><<<dim3(128, B_SZ), 256>>>(raw, dec_g2, dec_bt2, hBh, hBl, nullptr);
    wprep_k<<<(5*128*640+255)/256, 256>>>(dec_w3, wh, wl, 640, 80, 640, 128, 5, 1, 1);
    GEMM5(640, 1, hBh, hBl, 512, yeh, yel, dec_b3, 80, 128);
    out_k<<<dim3(T_LEN/32, B_SZ), 256>>>(raw, outp);
}

// round 11
// speedup vs baseline: 8.8837x; 1.2107x over previous
#include <cuda_runtime.h>
#include <cuda_fp16.h>
#include <cuda_bf16.h>
#include <math.h>
#include <stdint.h>

#define T_LEN 4096
#define B_SZ  16

// ---------------- scratch ----------------
__device__ float    g_raw  [16ll*1024*4096];
__device__ float    g_act32[16ll*512*4096];
__device__ float    g_z    [16ll*64*4096];
__device__ uint16_t g_hAh[16ll*4096*512], g_hAl[16ll*4096*512];
__device__ uint16_t g_hBh[16ll*4096*512], g_hBl[16ll*4096*512];
__device__ uint16_t g_xh [16ll*4096*128], g_xl [16ll*4096*128];
__device__ uint16_t g_yeh[16ll*4096*128];
__device__ uint16_t g_zvh[16ll*4096*64];
__device__ uint16_t g_wh [5ll*1024*640],  g_wl [5ll*1024*640];
__device__ float    g_wt [512*64];
__device__ float    g_cbt[64*512];
__device__ float    g_cbn[512];
__device__ float    g_spk[128*128];
__device__ int      g_idx[16*4096];

// ---------------- conversion helpers ----------------
__device__ __forceinline__ uint16_t f2bf(float v) {
    __nv_bfloat16 h = __float2bfloat16(v); return *(uint16_t*)&h;
}
__device__ __forceinline__ float bf2f(uint16_t u) {
    __nv_bfloat16 h = *(__nv_bfloat16*)&u; return __bfloat162float(h);
}
__device__ __forceinline__ uint16_t f2hf(float v) {
    __half h = __float2half(v); return *(uint16_t*)&h;
}

// ---------------- PTX helpers ----------------
__device__ __forceinline__ uint32_t s32(const void* p) {
    uint32_t a;
    asm("{ .reg .u64 t; cvta.to.shared.u64 t, %1; cvt.u32.u64 %0, t; }" : "=r"(a) : "l"(p));
    return a;
}
__device__ __forceinline__ void cpa16(uint32_t d, const void* s, bool v) {
    int sz = v ? 16 : 0;
    asm volatile("cp.async.cg.shared.global [%0], [%1], 16, %2;" :: "r"(d), "l"(s), "r"(sz) : "memory");
}
#define CP_COMMIT() asm volatile("cp.async.commit_group;" ::: "memory")
__device__ __forceinline__ void ldsm4(uint32_t* r, uint32_t a) {
    asm volatile("ldmatrix.sync.aligned.m8n8.x4.shared.b16 {%0,%1,%2,%3}, [%4];"
                 : "=r"(r[0]),"=r"(r[1]),"=r"(r[2]),"=r"(r[3]) : "r"(a));
}
__device__ __forceinline__ void ldsm2(uint32_t* r, uint32_t a) {
    asm volatile("ldmatrix.sync.aligned.m8n8.x2.shared.b16 {%0,%1}, [%2];"
                 : "=r"(r[0]),"=r"(r[1]) : "r"(a));
}
__device__ __forceinline__ void mma_bf16(float* d, const uint32_t* a, const uint32_t* b) {
    asm volatile("mma.sync.aligned.m16n8k16.row.col.f32.bf16.bf16.f32 "
                 "{%0,%1,%2,%3}, {%4,%5,%6,%7}, {%8,%9}, {%0,%1,%2,%3};"
                 : "+f"(d[0]), "+f"(d[1]), "+f"(d[2]), "+f"(d[3])
                 : "r"(a[0]), "r"(a[1]), "r"(a[2]), "r"(a[3]), "r"(b[0]), "r"(b[1]));
}
__device__ __forceinline__ void mma_f16(float* d, const uint32_t* a, const uint32_t* b) {
    asm volatile("mma.sync.aligned.m16n8k16.row.col.f32.f16.f16.f32 "
                 "{%0,%1,%2,%3}, {%4,%5,%6,%7}, {%8,%9}, {%0,%1,%2,%3};"
                 : "+f"(d[0]), "+f"(d[1]), "+f"(d[2]), "+f"(d[3])
                 : "r"(a[0]), "r"(a[1]), "r"(a[2]), "r"(a[3]), "r"(b[0]), "r"(b[1]));
}

// ---------------- mma.sync K=5 implicit conv GEMM ----------------
// MODE 0: bf16, A hi/lo + B hi/lo, 3 products (encoder — flip-free 2^-16)
// MODE 2: fp16, A single + B single, 1 product (decoder — ~2^-12/layer/source)
// grid (T/128, B, COUTP/128), block 256 (8 warps, warp tile 64co x 32t).
template<int CINP, int MODE>
__global__ void __launch_bounds__(256,2) gemm5_k(
    const uint16_t* __restrict__ in1h, const uint16_t* __restrict__ in1l, int C1,
    const uint16_t* __restrict__ in2h, const uint16_t* __restrict__ in2l,
    const uint16_t* __restrict__ wh,   const uint16_t* __restrict__ wl,
    const float* __restrict__ bias, int COUT, int COUTP,
    float* __restrict__ raw)
{
    constexpr int NCH  = CINP / 32;
    constexpr int ITER = NCH * 5;
    constexpr uint32_t B_BUF = (MODE == 0) ? 21120u : 10560u;
    constexpr uint32_t A_BUF = (MODE == 0) ? 20480u : 10240u;
    extern __shared__ char smc[];
    const uint32_t sb = s32(smc);
    const uint32_t B_OFF0 = 0u, B_OFF1 = B_BUF;
    const uint32_t A_OFF0 = 2u * B_BUF, A_OFF1 = 2u * B_BUF + A_BUF;

    const int tid = threadIdx.x, lane = tid & 31, wid = tid >> 5;
    const int mw = wid & 1, nw = wid >> 1;
    const int t0 = blockIdx.x * 128, b = blockIdx.y, mo = blockIdx.z;

    float acc[4][4][4];
    #pragma unroll
    for (int i = 0; i < 4; i++)
        #pragma unroll
        for (int j = 0; j < 4; j++)
            #pragma unroll
            for (int q = 0; q < 4; q++) acc[i][j][q] = 0.f;

    const uint32_t aRow = (uint32_t)(((lane >> 3) & 1) * 8 + (lane & 7));
    const uint32_t aCol = (uint32_t)((lane >> 4) * 16);
    const uint32_t bRow = (uint32_t)(lane & 7);
    const uint32_t bCol = (uint32_t)((((lane & 15) >> 3)) * 16);

    auto issueB = [&](int ch, uint32_t boff) {
        int ci0 = ch * 32;
        const uint16_t *srch, *srcl; int Cs, off;
        if (ci0 < C1) { srch = in1h; srcl = in1l; Cs = C1;        off = ci0; }
        else          { srch = in2h; srcl = in2l; Cs = CINP - C1; off = ci0 - C1; }
        constexpr int BE = (MODE == 0) ? 1056 : 528;   // 132 rows x 4 vec16 (x2 halves MODE0)
        for (int e = tid; e < BE; e += 256) {
            int half_ = (e >= 528); int ee = half_ ? e - 528 : e;
            int row = ee >> 2, v = ee & 3;
            int t = t0 - 2 + row;
            bool ok = (t >= 0) & (t < T_LEN);
            int tc = ok ? t : 0;
            uint32_t d = sb + boff + (uint32_t)half_ * 10560u + (uint32_t)row * 80u + (uint32_t)v * 16u;
            const uint16_t* s = (half_ ? srcl : srch) + ((size_t)b * T_LEN + tc) * Cs + off + v * 8;
            cpa16(d, s, ok);
        }
    };
    auto issueA = [&](int it, uint32_t aoff) {
        int ch = it / 5, k = it % 5, ci0 = ch * 32;
        constexpr int AE = (MODE == 0) ? 1024 : 512;   // 128 rows x 4 vec16 (x2 halves MODE0)
        for (int e = tid; e < AE; e += 256) {
            int half_ = (e >= 512); int ee = e & 511;
            int row = ee >> 2, v = ee & 3;
            uint32_t d = sb + aoff + (uint32_t)half_ * 10240u + (uint32_t)row * 80u + (uint32_t)v * 16u;
            const uint16_t* s = (half_ ? wl : wh) + ((size_t)k * COUTP + mo * 128 + row) * CINP + ci0 + v * 8;
            cpa16(d, s, true);
        }
    };

    issueB(0, B_OFF0);
    issueA(0, A_OFF0);
    CP_COMMIT();

    for (int it = 0; it < ITER; it++) {
        int ch = it / 5, k = it % 5;
        uint32_t aoff = (it & 1) ? A_OFF1 : A_OFF0;
        uint32_t boff = (ch & 1) ? B_OFF1 : B_OFF0;
        if (it + 1 < ITER) {
            int ch1 = (it + 1) / 5;
            if (ch1 != ch) issueB(ch1, (ch1 & 1) ? B_OFF1 : B_OFF0);
            issueA(it + 1, ((it + 1) & 1) ? A_OFF1 : A_OFF0);
            CP_COMMIT();
            asm volatile("cp.async.wait_group 1;" ::: "memory");
        } else {
            asm volatile("cp.async.wait_group 0;" ::: "memory");
        }
        __syncthreads();

        uint32_t aH = sb + aoff + (uint32_t)(mw * 64) * 80u;
        uint32_t bH = sb + boff + (uint32_t)(nw * 32 + k) * 80u;
        #pragma unroll
        for (int ks = 0; ks < 2; ks++) {
            uint32_t ah[4][4], bh[4][2];
            uint32_t kOff = (uint32_t)ks * 32u;
            #pragma unroll
            for (int mt = 0; mt < 4; mt++) ldsm4(ah[mt], aH + (uint32_t)(mt * 16) * 80u + aRow * 80u + kOff + aCol);
            #pragma unroll
            for (int nt = 0; nt < 4; nt++) ldsm2(bh[nt], bH + (uint32_t)(nt * 8) * 80u + bRow * 80u + kOff + bCol);
            #pragma unroll
            for (int mt = 0; mt < 4; mt++)
                #pragma unroll
                for (int nt = 0; nt < 4; nt++) {
                    if constexpr (MODE == 0) mma_bf16(acc[mt][nt], ah[mt], bh[nt]);
                    else                     mma_f16 (acc[mt][nt], ah[mt], bh[nt]);
                }
            if constexpr (MODE == 0) {
                uint32_t bl[4][2], al[4][4];
                uint32_t bL = bH + 10560u;
                uint32_t aL = aH + 10240u;
                #pragma unroll
                for (int nt = 0; nt < 4; nt++) ldsm2(bl[nt], bL + (uint32_t)(nt * 8) * 80u + bRow * 80u + kOff + bCol);
                #pragma unroll
                for (int mt = 0; mt < 4; mt++)
                    #pragma unroll
                    for (int nt = 0; nt < 4; nt++) mma_bf16(acc[mt][nt], ah[mt], bl[nt]);
                #pragma unroll
                for (int mt = 0; mt < 4; mt++) ldsm4(al[mt], aL + (uint32_t)(mt * 16) * 80u + aRow * 80u + kOff + aCol);
                #pragma unroll
                for (int mt = 0; mt < 4; mt++)
                    #pragma unroll
                    for (int nt = 0; nt < 4; nt++) mma_bf16(acc[mt][nt], al[mt], bh[nt]);
            }
        }
        __syncthreads();
    }

    // epilogue: bias + store raw [b][co][t]
    {
        int r = lane >> 2, c = (lane & 3) * 2;
        #pragma unroll
        for (int mt = 0; mt < 4; mt++) {
            int co0 = mo * 128 + mw * 64 + mt * 16 + r;
            int co1 = co0 + 8;
            float bv0 = (co0 < COUT) ? bias[co0] : 0.f;
            float bv1 = (co1 < COUT) ? bias[co1] : 0.f;
            #pragma unroll
            for (int nt = 0; nt < 4; nt++) {
                int t = t0 + nw * 32 + nt * 8 + c;
                float2 v0; v0.x = acc[mt][nt][0] + bv0; v0.y = acc[mt][nt][1] + bv0;
                float2 v1; v1.x = acc[mt][nt][2] + bv1; v1.y = acc[mt][nt][3] + bv1;
                *(float2*)(raw + ((size_t)b * COUTP + co0) * T_LEN + t) = v0;
                *(float2*)(raw + ((size_t)b * COUTP + co1) * T_LEN + t) = v1;
            }
        }
    }
}

// ---------------- LN + act + transpose + 16-bit output ----------------
// OUT: 0 = bf16 hi/lo pair, 1 = fp16 single, 2 = fp32 only
template<int CRAW,int GLU,int OUT,int EXF>
__global__ void __launch_bounds__(256) ln_k(const float* __restrict__ raw,
    const float* __restrict__ ga, const float* __restrict__ be,
    uint16_t* __restrict__ oh, uint16_t* __restrict__ ol, float* __restrict__ of)
{
    constexpr int COUT = GLU ? CRAW/2 : CRAW;
    __shared__ float sS[8][33], sQ[8][33], sM[32], sR[32];
    __shared__ uint16_t sTh[32*66], sTl[32*66];
    int b = blockIdx.y, t0 = blockIdx.x*32;
    int wg = threadIdx.x>>5, tt = threadIdx.x&31;
    const float* rb = raw + (size_t)b*CRAW*T_LEN + t0 + tt;
    float s=0.f, q=0.f;
    for (int c=wg; c<CRAW; c+=8){ float v=rb[(size_t)c*T_LEN]; s+=v; q+=v*v; }
    sS[wg][tt]=s; sQ[wg][tt]=q; __syncthreads();
    if (threadIdx.x<32){
        float S=0.f,Q=0.f;
        for(int g2=0;g2<8;g2++){S+=sS[g2][threadIdx.x];Q+=sQ[g2][threadIdx.x];}
        float m=S*(1.f/CRAW); float v=Q*(1.f/CRAW)-m*m;
        sM[threadIdx.x]=m; sR[threadIdx.x]=rsqrtf(v+1e-5f);
    }
    __syncthreads();
    float m=sM[tt], r=sR[tt];
    for (int c0=0;c0<COUT;c0+=64){
        #pragma unroll
        for (int i=0;i<8;i++){
            int c=c0+wg+8*i;
            float a=(rb[(size_t)c*T_LEN]-m)*r*ga[c]+be[c];
            if (GLU){
                float gt=(rb[(size_t)(c+COUT)*T_LEN]-m)*r*ga[c+COUT]+be[c+COUT];
                a=a*(1.f/(1.f+expf(-gt)));
            } else a = a>0.f? a : 0.2f*a;
            if (EXF) of[((size_t)b*COUT+c)*T_LEN + t0+tt] = a;
            if constexpr (OUT == 0) {
                uint16_t h = f2bf(a);
                sTh[tt*66 + wg+8*i] = h;
                sTl[tt*66 + wg+8*i] = f2bf(a - bf2f(h));
            } else if constexpr (OUT == 1) {
                sTh[tt*66 + wg+8*i] = f2hf(a);
            }
        }
        if constexpr (OUT != 2) {
            __syncthreads();
            {
                int row=threadIdx.x>>3, v=threadIdx.x&7;
                const uint32_t* ph=(const uint32_t*)sTh + row*33 + v*4;
                size_t go=((size_t)b*T_LEN + t0+row)*COUT + c0 + v*8;
                *(uint4*)(oh+go)=make_uint4(ph[0],ph[1],ph[2],ph[3]);
                if constexpr (OUT == 0) {
                    const uint32_t* pl=(const uint32_t*)sTl + row*33 + v*4;
                    *(uint4*)(ol+go)=make_uint4(pl[0],pl[1],pl[2],pl[3]);
                }
            }
            __syncthreads();
        }
    }
}

// ---------------- small helpers ----------------
__global__ void spknorm_k(const float* __restrict__ spk, float* __restrict__ o) {
    __shared__ float red[128];
    int r = blockIdx.x, t = threadIdx.x;
    float v = spk[r*128 + t];
    red[t] = v*v; __syncthreads();
    for (int s = 64; s > 0; s >>= 1) { if (t < s) red[t] += red[t+s]; __syncthreads(); }
    o[r*128 + t] = v * rsqrtf(red[0]);
}
__global__ void cbnorm_k(const float* __restrict__ cb, float* __restrict__ n) {
    int c = blockIdx.x*128 + threadIdx.x;
    if (c < 512) { float s=0.f; for (int d=0; d<64; d++){ float v=cb[c*64+d]; s+=v*v; } n[c]=s; }
}
__global__ void xprep_k(const float* __restrict__ x, uint16_t* __restrict__ oh, uint16_t* __restrict__ ol) {
    size_t e = (size_t)blockIdx.x*256 + threadIdx.x;
    int c = (int)(e & 127); size_t bt = e >> 7;
    float v = (c < 80) ? x[bt*80 + c] : 0.f;
    uint16_t h = f2bf(v);
    oh[e] = h; ol[e] = f2bf(v - bf2f(h));
}
__global__ void yeb_k(const int* __restrict__ y, const float* __restrict__ spk,
                      uint16_t* __restrict__ oh) {
    int b = blockIdx.y, t = blockIdx.x*8 + (threadIdx.x>>5), lid = threadIdx.x & 31;
    int yi = y[(size_t)b*T_LEN + t];
    size_t base = ((size_t)b*T_LEN + t) * 128;
    for (int c = lid; c < 128; c += 32)
        oh[base+c] = f2hf(spk[yi*128 + c]);
}
__global__ void zvqb_k(const int* __restrict__ idx, const float* __restrict__ cb,
                       uint16_t* __restrict__ oh) {
    int b = blockIdx.y, t = blockIdx.x*8 + (threadIdx.x>>5), lid = threadIdx.x & 31;
    int ii = idx[(size_t)b*T_LEN + t];
    size_t base = ((size_t)b*T_LEN + t) * 64;
    for (int c = lid; c < 64; c += 32)
        oh[base+c] = f2hf(cb[ii*64 + c]);
}
__global__ void out_k(const float* __restrict__ raw, float* __restrict__ out) {
    int b = blockIdx.y, tt = threadIdx.x & 31, g = threadIdx.x >> 5;
    int t = blockIdx.x*32 + tt;
    for (int f = g; f < 80; f += 8)
        out[((size_t)b*T_LEN + t)*80 + f] = raw[((size_t)b*128 + f)*T_LEN + t];
}
// mode 0: bf16 hi/lo (encoder); mode 1: fp16 single (decoder; dec handles ConvT flip)
__global__ void wprep_k(const float* __restrict__ w, uint16_t* __restrict__ wh, uint16_t* __restrict__ wl,
                        int CIN, int COUT, int CINP, int COUTP, int K, int dec, int mode) {
    long e = (long)blockIdx.x*256 + threadIdx.x;
    if (e >= (long)K*COUTP*CINP) return;
    int ci = (int)(e % CINP); long r0 = e / CINP; int co = (int)(r0 % COUTP); int k = (int)(r0 / COUTP);
    float v = 0.f;
    if (ci < CIN && co < COUT)
        v = dec ? w[((size_t)ci*COUT + co)*K + (K-1-k)] : w[((size_t)co*CIN + ci)*K + k];
    if (mode == 0) {
        uint16_t h = f2bf(v);
        wh[e] = h; wl[e] = f2bf(v - bf2f(h));
    } else {
        wh[e] = f2hf(v);
    }
}
__global__ void wtrans_k(const float* __restrict__ w, float* __restrict__ wt, int CIN, int COUT) {
    int e = blockIdx.x*256 + threadIdx.x;
    if (e >= CIN*COUT) return;
    int co = e % COUT, ci = e / COUT;
    wt[e] = w[(size_t)co*CIN + ci];
}

// ---------------- fp32 1x1 conv (mlp / VQ argmin) ----------------
template<int CIN,int COUT,int G_CO,int TPT,int EPI>
__global__ __launch_bounds__(256,2) void mm_k(
    const float* __restrict__ in, const float* __restrict__ wt,
    const float* __restrict__ bias, float* __restrict__ out, int* __restrict__ oidx)
{
    constexpr int CIB=16, G_T=256/G_CO, TT=G_T*TPT, CPT=COUT/G_CO;
    constexpr int WE=CIB*COUT, IE=CIB*TT, NCB=CIN/CIB, RS=G_CO+1;
    extern __shared__ float smf[];
    float* sW=smf; float* sI=sW+WE; float* sRa=sI+IE; int* sRi=(int*)(sRa+TT*RS);
    const int tid=threadIdx.x, cg=tid%G_CO, tg=tid/G_CO;
    const int b=blockIdx.y, t0=blockIdx.x*TT;
    float acc[CPT][TPT];
    #pragma unroll
    for (int i=0;i<CPT;i++)
        #pragma unroll
        for (int t=0;t<TPT;t++) acc[i][t]=0.f;
    for (int cb=0; cb<NCB; cb++) {
        __syncthreads();
        const float* ws = wt + (size_t)cb*WE;
        for (int e=tid; e<WE; e+=256) sW[e]=ws[e];
        for (int e=tid; e<IE; e+=256) {
            int ci=e/TT, j=e%TT;
            sI[e] = in[((size_t)b*CIN + cb*CIB + ci)*T_LEN + t0 + j];
        }
        __syncthreads();
        #pragma unroll 1
        for (int ci=0; ci<CIB; ci++) {
            float rin[TPT];
            #pragma unroll
            for (int j=0;j<TPT;j++) rin[j]=sI[ci*TT + tg*TPT + j];
            #pragma unroll
            for (int i=0;i<CPT;i++) {
                float wv = sW[ci*COUT + cg + G_CO*i];
                #pragma unroll
                for (int t=0;t<TPT;t++) acc[i][t]=fmaf(wv, rin[t], acc[i][t]);
            }
        }
    }
    if constexpr (EPI == 1) {
        float bv[CPT];
        #pragma unroll
        for (int i=0;i<CPT;i++) bv[i]=bias[cg + G_CO*i];
        #pragma unroll
        for (int t=0;t<TPT;t++) {
            float best=3.4e38f; int bi=0;
            #pragma unroll
            for (int i=0;i<CPT;i++) {
                float v=bv[i]-2.f*acc[i][t]; int ii=cg+G_CO*i;
                if (v<best || (v==best && ii<bi)) { best=v; bi=ii; }
            }
            int tl=tg*TPT+t;
            sRa[tl*RS+cg]=best; sRi[tl*RS+cg]=bi;
        }
        __syncthreads();
        if (tid < TT) {
            float best=3.4e38f; int bi=0;
            for (int g=0; g<G_CO; g++) {
                float v=sRa[tid*RS+g]; int ii=sRi[tid*RS+g];
                if (v<best || (v==best && ii<bi)) { best=v; bi=ii; }
            }
            oidx[(size_t)b*T_LEN + t0 + tid] = bi;
        }
    } else {
        #pragma unroll
        for (int i=0;i<CPT;i++) {
            int co=cg+G_CO*i;
            float bv=bias[co];
            #pragma unroll
            for (int t=0;t<TPT;t++)
                out[((size_t)b*COUT+co)*T_LEN + t0 + tg*TPT + t] = acc[i][t]+bv;
        }
    }
}

// ---------------- launch ----------------
#define GEMM5(CINP_, MODE_, i1h,i1l,C1_, i2h,i2l, biasp, COUT_, COUTP_) do { \
    constexpr int SMB_ = ((MODE_) == 0) ? (2*21120 + 2*20480) : (2*10560 + 2*10240); \
    auto kf = &gemm5_k<CINP_, MODE_>; \
    cudaFuncSetAttribute(kf, cudaFuncAttributeMaxDynamicSharedMemorySize, SMB_); \
    kf<<<dim3(32, B_SZ, (COUTP_)/128), 256, SMB_>>>(i1h,i1l,C1_, i2h,i2l, wh,wl, biasp, COUT_, COUTP_, raw); \
} while (0)

extern "C" void kernel_launch(void* const* d_in, const int* in_sizes, int n_in,
                              void* d_out, int out_size) {
    (void)in_sizes; (void)n_in; (void)out_size;
    const float* x       = (const float*)d_in[0];
    const int*   y       = (const int*)  d_in[1];
    const float* enc_w1  = (const float*)d_in[2];
    const float* enc_b1  = (const float*)d_in[3];
    const float* enc_g1  = (const float*)d_in[4];
    const float* enc_bt1 = (const float*)d_in[5];
    const float* enc_w2  = (const float*)d_in[6];
    const float* enc_b2  = (const float*)d_in[7];
    const float* enc_g2  = (const float*)d_in[8];
    const float* enc_bt2 = (const float*)d_in[9];
    const float* enc_w3  = (const float*)d_in[10];
    const float* enc_b3  = (const float*)d_in[11];
    const float* enc_g3  = (const float*)d_in[12];
    const float* enc_bt3 = (const float*)d_in[13];
    const float* mlp_w   = (const float*)d_in[14];
    const float* mlp_b   = (const float*)d_in[15];
    const float* codebook= (const float*)d_in[16];
    const float* spk_emb = (const float*)d_in[17];
    const float* dec_w1  = (const float*)d_in[18];
    const float* dec_b1  = (const float*)d_in[19];
    const float* dec_g1  = (const float*)d_in[20];
    const float* dec_bt1 = (const float*)d_in[21];
    const float* dec_w2  = (const float*)d_in[22];
    const float* dec_b2  = (const float*)d_in[23];
    const float* dec_g2  = (const float*)d_in[24];
    const float* dec_bt2 = (const float*)d_in[25];
    const float* dec_w3  = (const float*)d_in[26];
    const float* dec_b3  = (const float*)d_in[27];
    float* outp = (float*)d_out;

    float *raw,*act32,*z,*wt,*cbt,*cbn,*spk; int* idx;
    uint16_t *hAh,*hAl,*hBh,*hBl,*xh,*xl,*yeh,*zvh,*wh,*wl;
    cudaGetSymbolAddress((void**)&raw,  g_raw);
    cudaGetSymbolAddress((void**)&act32,g_act32);
    cudaGetSymbolAddress((void**)&z,    g_z);
    cudaGetSymbolAddress((void**)&hAh,  g_hAh);  cudaGetSymbolAddress((void**)&hAl, g_hAl);
    cudaGetSymbolAddress((void**)&hBh,  g_hBh);  cudaGetSymbolAddress((void**)&hBl, g_hBl);
    cudaGetSymbolAddress((void**)&xh,   g_xh);   cudaGetSymbolAddress((void**)&xl,  g_xl);
    cudaGetSymbolAddress((void**)&yeh,  g_yeh);
    cudaGetSymbolAddress((void**)&zvh,  g_zvh);
    cudaGetSymbolAddress((void**)&wh,   g_wh);   cudaGetSymbolAddress((void**)&wl,  g_wl);
    cudaGetSymbolAddress((void**)&wt,   g_wt);
    cudaGetSymbolAddress((void**)&cbt,  g_cbt);
    cudaGetSymbolAddress((void**)&cbn,  g_cbn);
    cudaGetSymbolAddress((void**)&spk,  g_spk);
    cudaGetSymbolAddress((void**)&idx,  g_idx);

    // input prep
    xprep_k<<<(B_SZ*T_LEN*128)/256, 256>>>(x, xh, xl);
    spknorm_k<<<128, 128>>>(spk_emb, spk);
    yeb_k<<<dim3(T_LEN/8, B_SZ), 256>>>(y, spk, yeh);

    // ===== encoder: bf16 3-product (MODE 0) =====
    wprep_k<<<(5*512*128+255)/256, 256>>>(enc_w1, wh, wl, 80, 512, 128, 512, 5, 0, 0);
    GEMM5(128, 0, xh, xl, 128, (const uint16_t*)nullptr, (const uint16_t*)nullptr, enc_b1, 512, 512);
    ln_k<512,0,0,0><<<dim3(128, B_SZ), 256>>>(raw, enc_g1, enc_bt1, hAh, hAl, nullptr);
    wprep_k<<<(5*512*512+255)/256, 256>>>(enc_w2, wh, wl, 512, 512, 512, 512, 5, 0, 0);
    GEMM5(512, 0, hAh, hAl, 512, (const uint16_t*)nullptr, (const uint16_t*)nullptr, enc_b2, 512, 512);
    ln_k<512,0,0,0><<<dim3(128, B_SZ), 256>>>(raw, enc_g2, enc_bt2, hBh, hBl, nullptr);
    wprep_k<<<(5*512*512+255)/256, 256>>>(enc_w3, wh, wl, 512, 512, 512, 512, 5, 0, 0);
    GEMM5(512, 0, hBh, hBl, 512, (const uint16_t*)nullptr, (const uint16_t*)nullptr, enc_b3, 512, 512);
    ln_k<512,0,2,1><<<dim3(128, B_SZ), 256>>>(raw, enc_g3, enc_bt3, nullptr, nullptr, act32);

    // ===== mlp + VQ (exact fp32) =====
    wtrans_k<<<(512*64+255)/256, 256>>>(mlp_w, wt, 512, 64);
    mm_k<512,64,32,8,0><<<dim3(T_LEN/64, B_SZ), 256, (16*64+16*64+64*33*2)*4>>>(act32, wt, mlp_b, z, nullptr);
    wtrans_k<<<(64*512+255)/256, 256>>>(codebook, cbt, 64, 512);
    cbnorm_k<<<4, 128>>>(codebook, cbn);
    {
        constexpr int SB = (16*512 + 16*32 + 32*65*2)*4;
        auto kf = &mm_k<64,512,64,8,1>;
        cudaFuncSetAttribute(kf, cudaFuncAttributeMaxDynamicSharedMemorySize, SB);
        kf<<<dim3(T_LEN/32, B_SZ), 256, SB>>>(z, cbt, cbn, nullptr, idx);
    }
    zvqb_k<<<dim3(T_LEN/8, B_SZ), 256>>>(idx, codebook, zvh);

    // ===== decoder: fp16 1-product (MODE 2) =====
    wprep_k<<<(5*1024*192+255)/256, 256>>>(dec_w1, wh, wl, 192, 1024, 192, 1024, 5, 1, 1);
    GEMM5(192, 2, zvh, (const uint16_t*)nullptr, 64, yeh, (const uint16_t*)nullptr, dec_b1, 1024, 1024);
    ln_k<1024,1,1,0><<<dim3(128, B_SZ), 256>>>(raw, dec_g1, dec_bt1, hAh, nullptr, nullptr);
    wprep_k<<<(5*1024*640+255)/256, 256>>>(dec_w2, wh, wl, 640, 1024, 640, 1024, 5, 1, 1);
    GEMM5(640, 2, hAh, (const uint16_t*)nullptr, 512, yeh, (const uint16_t*)nullptr, dec_b2, 1024, 1024);
    ln_k<1024,1,1,0><<<dim3(128, B_SZ), 256>>>(raw, dec_g2, dec_bt2, hBh, nullptr, nullptr);
    wprep_k<<<(5*128*640+255)/256, 256>>>(dec_w3, wh, wl, 640, 80, 640, 128, 5, 1, 1);
    GEMM5(640, 2, hBh, (const uint16_t*)nullptr, 512, yeh, (const uint16_t*)nullptr, dec_b3, 80, 128);
    out_k<<<dim3(T_LEN/32, B_SZ), 256>>>(raw, outp);
}